// round 2
// baseline (speedup 1.0000x reference)
#include <cuda_runtime.h>
#include <cstdint>
#include <cstddef>

// ---- static problem sizes (match reference) ----
#define Bg 128
#define Nn 256
#define Dd 128
#define Kk 16
#define Mm 16
#define CG_ITERS 10
#define SINK_ITERS 50
#define CAP 128          // max unique neighbors per row
#define STR 20           // smem staging stride in floats (80B, 16B-aligned)

// ---- device scratch (static allocation only; no cudaMalloc) ----
__device__ float           g_C[(size_t)Bg * Nn * Nn];      // dense adjacency counts
__device__ float           g_val[(size_t)Bg * Nn * CAP];   // CSR values (counts)
__device__ unsigned short  g_col[(size_t)Bg * Nn * CAP];   // CSR cols (within graph)
__device__ int             g_cnt[Bg * Nn];                 // CSR row lengths
__device__ float           g_cc1[Bg * Nn];                 // (C1^2 @ p)_i

// ============================ precompute ============================

__global__ void k_zero()
{
    size_t n = (size_t)Bg * Nn * Nn;
    for (size_t i = (size_t)blockIdx.x * blockDim.x + threadIdx.x; i < n;
         i += (size_t)gridDim.x * blockDim.x)
        g_C[i] = 0.f;
}

__global__ void k_scatter(const int* __restrict__ ei, int E)
{
    int e = blockIdx.x * blockDim.x + threadIdx.x;
    if (e >= E) return;
    int s = ei[e];
    int t = ei[E + e];
    int g = s >> 8;
    atomicAdd(&g_C[((size_t)(g * Nn + (s & 255))) * Nn + (t & 255)], 1.f);
}

__global__ void k_csr()
{
    int w = (blockIdx.x * blockDim.x + threadIdx.x) >> 5;
    int lane = threadIdx.x & 31;
    if (w >= Bg * Nn) return;
    const float* Crow = g_C + (size_t)w * Nn;
    float s2 = 0.f;
    int out = 0;
    size_t base = (size_t)w * CAP;
    for (int c0 = 0; c0 < Nn; c0 += 32) {
        float v = Crow[c0 + lane];
        s2 += v * v;
        unsigned m = __ballot_sync(0xffffffffu, v != 0.f);
        int off = __popc(m & ((1u << lane) - 1u));
        if (v != 0.f && (out + off) < CAP) {
            g_val[base + out + off] = v;
            g_col[base + out + off] = (unsigned short)(c0 + lane);
        }
        out += __popc(m);
    }
    #pragma unroll
    for (int o = 16; o; o >>= 1) s2 += __shfl_xor_sync(0xffffffffu, s2, o);
    if (lane == 0) {
        g_cnt[w] = out > CAP ? CAP : out;
        g_cc1[w] = s2 * (1.f / Nn);
    }
}

// ============================ main kernel ============================

__device__ __forceinline__ float ex2(float x)
{
    float r; asm("ex2.approx.ftz.f32 %0, %1;" : "=f"(r) : "f"(x)); return r;
}
__device__ __forceinline__ float lg2(float x)
{
    float r; asm("lg2.approx.ftz.f32 %0, %1;" : "=f"(r) : "f"(x)); return r;
}

__device__ __forceinline__ void spmm_row(const float* sT, size_t cbase, int cnt,
                                         float R[16])
{
    #pragma unroll
    for (int j = 0; j < 16; j++) R[j] = 0.f;
    for (int e = 0; e < cnt; e++) {
        int   c  = g_col[cbase + e];
        float vv = g_val[cbase + e];
        const float4* tp = (const float4*)(sT + c * STR);
        float4 t0 = tp[0], t1 = tp[1], t2 = tp[2], t3 = tp[3];
        R[0]  += vv * t0.x; R[1]  += vv * t0.y; R[2]  += vv * t0.z; R[3]  += vv * t0.w;
        R[4]  += vv * t1.x; R[5]  += vv * t1.y; R[6]  += vv * t1.z; R[7]  += vv * t1.w;
        R[8]  += vv * t2.x; R[9]  += vv * t2.y; R[10] += vv * t2.z; R[11] += vv * t2.w;
        R[12] += vv * t3.x; R[13] += vv * t3.y; R[14] += vv * t3.z; R[15] += vv * t3.w;
    }
}

__global__ __launch_bounds__(256, 2)
void k_fgw(const float* __restrict__ x,
           const float* __restrict__ tA,
           const float* __restrict__ tF,
           const float* __restrict__ q0,
           const float* __restrict__ a0,
           float* __restrict__ out)
{
    __shared__ __align__(16) float sT[Nn * STR];   // staging (features / T / dT / negC transpose)
    __shared__ __align__(16) float sC2[Mm * Mm];
    __shared__ __align__(16) float sG[Mm];         // Sinkhorn G (log2)
    __shared__ __align__(16) float sF[Nn];         // Sinkhorn F (log2)
    __shared__ float scc2[Mm];
    __shared__ float slogq2[Mm];
    __shared__ float sq[Mm];
    __shared__ float sFn[Mm];
    __shared__ float sred[8 * 4];
    __shared__ float sScal[4];
    __shared__ int   sFlag[2];

    const int tid  = threadIdx.x;
    const int bid  = blockIdx.x;
    const int b    = bid >> 4;
    const int k    = bid & 15;
    const int lane = tid & 31;
    const int wid  = tid >> 5;
    const float L2E = 1.44269504088896340736f;
    const float LOGP2 = -8.0f;                     // log2(1/256)
    const float EPS = 1e-5f;

    const float alpha = 1.f / (1.f + expf(-a0[0]));

    // --- load C2, q softmax, features ---
    sC2[tid] = tA[k * 256 + tid];
    if (tid == 0) {
        float qv[16], mq = -1e30f;
        #pragma unroll
        for (int j = 0; j < 16; j++) { qv[j] = q0[k * 16 + j]; mq = fmaxf(mq, qv[j]); }
        float s = 0.f;
        #pragma unroll
        for (int j = 0; j < 16; j++) { qv[j] = ex2((qv[j] - mq) * L2E); s += qv[j]; }
        float inv = 1.f / s;
        #pragma unroll
        for (int j = 0; j < 16; j++) {
            float qq = qv[j] * inv;
            sq[j] = qq;
            slogq2[j] = lg2(qq);
        }
        sFlag[0] = 0; sFlag[1] = 0;
    }
    for (int t = tid; t < Mm * Dd; t += 256) sT[t] = tF[k * Mm * Dd + t];
    __syncthreads();

    if (tid < 16) {
        float s = 0.f;
        #pragma unroll
        for (int l = 0; l < 16; l++) { float c = sC2[tid * 16 + l]; s += c * c * sq[l]; }
        scc2[tid] = s;
        float fn = 0.f;
        for (int d = 0; d < Dd; d++) { float f = sT[tid * Dd + d]; fn += f * f; }
        sFn[tid] = fn;
    }

    // --- Mcost row ---
    float Mr[16];
    #pragma unroll
    for (int j = 0; j < 16; j++) Mr[j] = 0.f;
    float xn = 0.f;
    const float4* xr = (const float4*)(x + ((size_t)(b * Nn + tid)) * Dd);
    for (int d4 = 0; d4 < Dd / 4; d4++) {
        float4 xv = xr[d4];
        xn += xv.x * xv.x + xv.y * xv.y + xv.z * xv.z + xv.w * xv.w;
        #pragma unroll
        for (int j = 0; j < 16; j++) {
            float4 fv = ((const float4*)sT)[j * (Dd / 4) + d4];
            Mr[j] += xv.x * fv.x + xv.y * fv.y + xv.z * fv.z + xv.w * fv.w;
        }
    }
    __syncthreads();
    #pragma unroll
    for (int j = 0; j < 16; j++) Mr[j] = xn + sFn[j] - 2.f * Mr[j];

    const int grow = b * Nn + tid;
    const int cnt = g_cnt[grow];
    const size_t cbase = (size_t)grow * CAP;
    const float cc1 = g_cc1[grow];

    float T[16];
    #pragma unroll
    for (int j = 0; j < 16; j++) T[j] = sq[j] * (1.f / Nn);

    float CTC[16];
    const int cj = tid >> 4, cs = tid & 15;   // column thread: column cj, rows cs*16..cs*16+15

    for (int it = 0; it <= CG_ITERS; it++) {
        // ===== CTC = C1 @ T @ C2^T =====
        {
            float4* st = (float4*)(sT + tid * STR);
            st[0] = make_float4(T[0], T[1], T[2], T[3]);
            st[1] = make_float4(T[4], T[5], T[6], T[7]);
            st[2] = make_float4(T[8], T[9], T[10], T[11]);
            st[3] = make_float4(T[12], T[13], T[14], T[15]);
        }
        __syncthreads();
        float R[16];
        spmm_row(sT, cbase, cnt, R);
        __syncthreads();
        #pragma unroll
        for (int jj = 0; jj < 16; jj++) {
            float s = 0.f;
            #pragma unroll
            for (int l4 = 0; l4 < 4; l4++) {
                float4 c4 = ((const float4*)sC2)[jj * 4 + l4];
                s += R[l4 * 4 + 0] * c4.x + R[l4 * 4 + 1] * c4.y
                   + R[l4 * 4 + 2] * c4.z + R[l4 * 4 + 3] * c4.w;
            }
            CTC[jj] = s;
        }
        if (it == CG_ITERS) break;

        // ===== grad -> negC (fixed for whole Sinkhorn loop), reg scale =====
        float negC[16];
        float mxa = 0.f;
        #pragma unroll
        for (int j = 0; j < 16; j++) {
            float g = (1.f - alpha) * Mr[j]
                    + 2.f * alpha * (cc1 + scc2[j] - 2.f * CTC[j]);
            negC[j] = g;
            mxa = fmaxf(mxa, fabsf(g));
        }
        #pragma unroll
        for (int o = 16; o; o >>= 1) mxa = fmaxf(mxa, __shfl_xor_sync(0xffffffffu, mxa, o));
        if (lane == 0) sred[wid] = mxa;
        __syncthreads();
        if (tid == 0) {
            float m = sred[0];
            #pragma unroll
            for (int w = 1; w < 8; w++) m = fmaxf(m, sred[w]);
            sScal[0] = m;
        }
        if (tid < 16) sG[tid] = 0.f;
        if (tid < 2)  sFlag[tid] = 0;
        __syncthreads();
        {
            float cscale = -L2E / (0.01f * sScal[0] + 1e-12f);
            #pragma unroll
            for (int j = 0; j < 16; j++) negC[j] *= cscale;
        }

        // ===== build transposed negC in registers (fixed across Sinkhorn) =====
        float negCT[16];
        {
            float4* st = (float4*)(sT + tid * STR);
            st[0] = make_float4(negC[0], negC[1], negC[2], negC[3]);
            st[1] = make_float4(negC[4], negC[5], negC[6], negC[7]);
            st[2] = make_float4(negC[8], negC[9], negC[10], negC[11]);
            st[3] = make_float4(negC[12], negC[13], negC[14], negC[15]);
        }
        __syncthreads();
        #pragma unroll
        for (int r = 0; r < 16; r++)
            negCT[r] = sT[(cs * 16 + r) * STR + cj];
        __syncthreads();

        // ===== Sinkhorn (log2 domain) =====
        float F2 = 0.f;
        for (int sk = 0; sk < SINK_ITERS; sk++) {
            int p = sk & 1;
            // --- F update (row-local): LSE over j of negC[j] + G[j] ---
            const float4* gp = (const float4*)sG;
            float m = -1e30f;
            float4 g0 = gp[0], g1 = gp[1], g2 = gp[2], g3 = gp[3];
            {
                m = fmaxf(m, negC[0]  + g0.x); m = fmaxf(m, negC[1]  + g0.y);
                m = fmaxf(m, negC[2]  + g0.z); m = fmaxf(m, negC[3]  + g0.w);
                m = fmaxf(m, negC[4]  + g1.x); m = fmaxf(m, negC[5]  + g1.y);
                m = fmaxf(m, negC[6]  + g1.z); m = fmaxf(m, negC[7]  + g1.w);
                m = fmaxf(m, negC[8]  + g2.x); m = fmaxf(m, negC[9]  + g2.y);
                m = fmaxf(m, negC[10] + g2.z); m = fmaxf(m, negC[11] + g2.w);
                m = fmaxf(m, negC[12] + g3.x); m = fmaxf(m, negC[13] + g3.y);
                m = fmaxf(m, negC[14] + g3.z); m = fmaxf(m, negC[15] + g3.w);
            }
            float s = 0.f;
            {
                s += ex2(negC[0]  + g0.x - m); s += ex2(negC[1]  + g0.y - m);
                s += ex2(negC[2]  + g0.z - m); s += ex2(negC[3]  + g0.w - m);
                s += ex2(negC[4]  + g1.x - m); s += ex2(negC[5]  + g1.y - m);
                s += ex2(negC[6]  + g1.z - m); s += ex2(negC[7]  + g1.w - m);
                s += ex2(negC[8]  + g2.x - m); s += ex2(negC[9]  + g2.y - m);
                s += ex2(negC[10] + g2.z - m); s += ex2(negC[11] + g2.w - m);
                s += ex2(negC[12] + g3.x - m); s += ex2(negC[13] + g3.y - m);
                s += ex2(negC[14] + g3.z - m); s += ex2(negC[15] + g3.w - m);
            }
            F2 = LOGP2 - (m + lg2(s));
            sF[tid] = F2;
            __syncthreads();

            // --- G update (column): LSE over i of negC[i][cj] + F[i] ---
            float Fv[16];
            {
                const float4* fp = (const float4*)(sF + cs * 16);
                float4 a = fp[0], bb = fp[1], c = fp[2], d = fp[3];
                Fv[0]=a.x; Fv[1]=a.y; Fv[2]=a.z; Fv[3]=a.w;
                Fv[4]=bb.x; Fv[5]=bb.y; Fv[6]=bb.z; Fv[7]=bb.w;
                Fv[8]=c.x; Fv[9]=c.y; Fv[10]=c.z; Fv[11]=c.w;
                Fv[12]=d.x; Fv[13]=d.y; Fv[14]=d.z; Fv[15]=d.w;
            }
            float cm = -1e30f;
            #pragma unroll
            for (int r = 0; r < 16; r++) { Fv[r] += negCT[r]; cm = fmaxf(cm, Fv[r]); }
            #pragma unroll
            for (int o = 8; o; o >>= 1) cm = fmaxf(cm, __shfl_xor_sync(0xffffffffu, cm, o));
            float ss = 0.f;
            #pragma unroll
            for (int r = 0; r < 16; r++) ss += ex2(Fv[r] - cm);
            #pragma unroll
            for (int o = 8; o; o >>= 1) ss += __shfl_xor_sync(0xffffffffu, ss, o);
            if (cs == 0) {
                float gn = slogq2[cj] - (cm + lg2(ss));
                if (fabsf(gn - sG[cj]) > EPS) sFlag[p] = 1;
                sG[cj] = gn;
                if (cj == 0) sFlag[p ^ 1] = 0;   // pre-clear other parity
            }
            __syncthreads();
            if (sFlag[p] == 0) break;            // converged: remaining iters are no-ops
        }

        // ===== Tnew, dT =====
        float dT[16];
        {
            const float4* gp = (const float4*)sG;
            float4 g0 = gp[0], g1 = gp[1], g2 = gp[2], g3 = gp[3];
            float Gv[16] = { g0.x,g0.y,g0.z,g0.w, g1.x,g1.y,g1.z,g1.w,
                             g2.x,g2.y,g2.z,g2.w, g3.x,g3.y,g3.z,g3.w };
            #pragma unroll
            for (int j = 0; j < 16; j++)
                dT[j] = ex2(negC[j] + F2 + Gv[j]) - T[j];
        }
        __syncthreads();   // done reading sG; sT free for restage

        // ===== D = C1 @ dT @ C2^T =====
        {
            float4* st = (float4*)(sT + tid * STR);
            st[0] = make_float4(dT[0], dT[1], dT[2], dT[3]);
            st[1] = make_float4(dT[4], dT[5], dT[6], dT[7]);
            st[2] = make_float4(dT[8], dT[9], dT[10], dT[11]);
            st[3] = make_float4(dT[12], dT[13], dT[14], dT[15]);
        }
        __syncthreads();
        float Rd[16];
        spmm_row(sT, cbase, cnt, Rd);
        __syncthreads();
        float D[16];
        #pragma unroll
        for (int jj = 0; jj < 16; jj++) {
            float s = 0.f;
            #pragma unroll
            for (int l4 = 0; l4 < 4; l4++) {
                float4 c4 = ((const float4*)sC2)[jj * 4 + l4];
                s += Rd[l4 * 4 + 0] * c4.x + Rd[l4 * 4 + 1] * c4.y
                   + Rd[l4 * 4 + 2] * c4.z + Rd[l4 * 4 + 3] * c4.w;
            }
            D[jj] = s;
        }

        // ===== line search =====
        float pa = 0.f, pb1 = 0.f, pb2 = 0.f, pb3 = 0.f;
        #pragma unroll
        for (int j = 0; j < 16; j++) {
            pa  += D[j] * dT[j];
            pb1 += Mr[j] * dT[j];
            pb2 += D[j] * T[j];
            pb3 += CTC[j] * dT[j];
        }
        #pragma unroll
        for (int o = 16; o; o >>= 1) {
            pa  += __shfl_xor_sync(0xffffffffu, pa, o);
            pb1 += __shfl_xor_sync(0xffffffffu, pb1, o);
            pb2 += __shfl_xor_sync(0xffffffffu, pb2, o);
            pb3 += __shfl_xor_sync(0xffffffffu, pb3, o);
        }
        if (lane == 0) {
            sred[wid * 4 + 0] = pa;  sred[wid * 4 + 1] = pb1;
            sred[wid * 4 + 2] = pb2; sred[wid * 4 + 3] = pb3;
        }
        __syncthreads();
        if (tid == 0) {
            float Sa = 0.f, S1 = 0.f, S2 = 0.f, S3 = 0.f;
            #pragma unroll
            for (int w = 0; w < 8; w++) {
                Sa += sred[w * 4 + 0]; S1 += sred[w * 4 + 1];
                S2 += sred[w * 4 + 2]; S3 += sred[w * 4 + 3];
            }
            float A  = -2.f * alpha * Sa;
            float Bc = (1.f - alpha) * S1 - 2.f * alpha * (S2 + S3);
            float tstep;
            if (A > 0.f) {
                tstep = -Bc / (2.f * A + 1e-16f);
                tstep = fminf(1.f, fmaxf(0.f, tstep));
            } else {
                tstep = (A + Bc < 0.f) ? 1.f : 0.f;
            }
            sScal[1] = tstep;
        }
        __syncthreads();
        float ts = sScal[1];
        #pragma unroll
        for (int j = 0; j < 16; j++) T[j] += ts * dT[j];
    }

    // ===== epilogue =====
    float pg = 0.f, pl = 0.f;
    #pragma unroll
    for (int j = 0; j < 16; j++) {
        pg += (cc1 + scc2[j] - 2.f * CTC[j]) * T[j];
        pl += Mr[j] * T[j];
    }
    #pragma unroll
    for (int o = 16; o; o >>= 1) {
        pg += __shfl_xor_sync(0xffffffffu, pg, o);
        pl += __shfl_xor_sync(0xffffffffu, pl, o);
    }
    if (lane == 0) { sred[wid * 2] = pg; sred[wid * 2 + 1] = pl; }
    __syncthreads();
    if (tid == 0) {
        float Gw = 0.f, L = 0.f;
        #pragma unroll
        for (int w = 0; w < 8; w++) { Gw += sred[w * 2]; L += sred[w * 2 + 1]; }
        out[bid] = (1.f - alpha) * L + alpha * Gw;
    }
}

// ============================ launch ============================

extern "C" void kernel_launch(void* const* d_in, const int* in_sizes, int n_in,
                              void* d_out, int out_size)
{
    const float* x  = (const float*)d_in[0];
    const int*   ei = (const int*)  d_in[1];
    const float* tA = (const float*)d_in[3];
    const float* tF = (const float*)d_in[4];
    const float* q0 = (const float*)d_in[5];
    const float* a0 = (const float*)d_in[6];
    int E = in_sizes[1] / 2;

    k_zero<<<8192, 256>>>();
    k_scatter<<<(E + 255) / 256, 256>>>(ei, E);
    k_csr<<<(Bg * Nn * 32 + 255) / 256, 256>>>();
    k_fgw<<<Bg * Kk, 256>>>(x, tA, tF, q0, a0, (float*)d_out);
}

// round 3
// speedup vs baseline: 1.2153x; 1.2153x over previous
#include <cuda_runtime.h>
#include <cstdint>
#include <cstddef>

// ---- static problem sizes (match reference) ----
#define Bg 128
#define Nn 256
#define Dd 128
#define Kk 16
#define Mm 16
#define CG_ITERS 10
#define SINK_ITERS 50
#define CAP 128          // max unique neighbors per row
#define STR 20           // smem staging stride in floats (80B, 16B-aligned)

// padded index for the uf staging buffer: 16 consecutive floats per cs-block,
// blocks offset by 20 -> LDS.128 reads ~2-way instead of 16-way conflicted
#define FPAD(i) ((i) + 4 * ((i) >> 4))

// ---- device scratch ----
__device__ float           g_C[(size_t)Bg * Nn * Nn];
__device__ float           g_val[(size_t)Bg * Nn * CAP];
__device__ unsigned short  g_col[(size_t)Bg * Nn * CAP];
__device__ int             g_cnt[Bg * Nn];
__device__ float           g_cc1[Bg * Nn];

// ============================ precompute ============================

__global__ void k_zero()
{
    size_t n = (size_t)Bg * Nn * Nn;
    for (size_t i = (size_t)blockIdx.x * blockDim.x + threadIdx.x; i < n;
         i += (size_t)gridDim.x * blockDim.x)
        g_C[i] = 0.f;
}

__global__ void k_scatter(const int* __restrict__ ei, int E)
{
    int e = blockIdx.x * blockDim.x + threadIdx.x;
    if (e >= E) return;
    int s = ei[e];
    int t = ei[E + e];
    int g = s >> 8;
    atomicAdd(&g_C[((size_t)(g * Nn + (s & 255))) * Nn + (t & 255)], 1.f);
}

__global__ void k_csr()
{
    int w = (blockIdx.x * blockDim.x + threadIdx.x) >> 5;
    int lane = threadIdx.x & 31;
    if (w >= Bg * Nn) return;
    const float* Crow = g_C + (size_t)w * Nn;
    float s2 = 0.f;
    int out = 0;
    size_t base = (size_t)w * CAP;
    for (int c0 = 0; c0 < Nn; c0 += 32) {
        float v = Crow[c0 + lane];
        s2 += v * v;
        unsigned m = __ballot_sync(0xffffffffu, v != 0.f);
        int off = __popc(m & ((1u << lane) - 1u));
        if (v != 0.f && (out + off) < CAP) {
            g_val[base + out + off] = v;
            g_col[base + out + off] = (unsigned short)(c0 + lane);
        }
        out += __popc(m);
    }
    #pragma unroll
    for (int o = 16; o; o >>= 1) s2 += __shfl_xor_sync(0xffffffffu, s2, o);
    if (lane == 0) {
        g_cnt[w] = out > CAP ? CAP : out;
        g_cc1[w] = s2 * (1.f / Nn);
    }
}

// ============================ main kernel ============================

__device__ __forceinline__ float ex2(float x)
{
    float r; asm("ex2.approx.ftz.f32 %0, %1;" : "=f"(r) : "f"(x)); return r;
}
__device__ __forceinline__ float lg2(float x)
{
    float r; asm("lg2.approx.ftz.f32 %0, %1;" : "=f"(r) : "f"(x)); return r;
}

__device__ __forceinline__ void spmm_row(const float* sT, size_t cbase, int cnt,
                                         float R[16])
{
    #pragma unroll
    for (int j = 0; j < 16; j++) R[j] = 0.f;
    for (int e = 0; e < cnt; e++) {
        int   c  = g_col[cbase + e];
        float vv = g_val[cbase + e];
        const float4* tp = (const float4*)(sT + c * STR);
        float4 t0 = tp[0], t1 = tp[1], t2 = tp[2], t3 = tp[3];
        R[0]  += vv * t0.x; R[1]  += vv * t0.y; R[2]  += vv * t0.z; R[3]  += vv * t0.w;
        R[4]  += vv * t1.x; R[5]  += vv * t1.y; R[6]  += vv * t1.z; R[7]  += vv * t1.w;
        R[8]  += vv * t2.x; R[9]  += vv * t2.y; R[10] += vv * t2.z; R[11] += vv * t2.w;
        R[12] += vv * t3.x; R[13] += vv * t3.y; R[14] += vv * t3.z; R[15] += vv * t3.w;
    }
}

__global__ __launch_bounds__(256, 2)
void k_fgw(const float* __restrict__ x,
           const float* __restrict__ tA,
           const float* __restrict__ tF,
           const float* __restrict__ q0,
           const float* __restrict__ a0,
           float* __restrict__ out)
{
    __shared__ __align__(16) float sT[Nn * STR];     // staging (features / T / dT / negC^T)
    __shared__ __align__(16) float sC2[Mm * Mm];
    __shared__ __align__(16) float sG[Mm];           // G (log2)
    __shared__ __align__(16) float sVg[Mm];          // 2^(G - gmax)
    __shared__ __align__(16) float sCS[Mm];          // column sums
    __shared__ __align__(16) float scmx[Mm];         // cmax_j
    __shared__ __align__(16) float sFp[Nn + Nn / 4]; // padded uf buffer
    __shared__ float scc2[Mm];
    __shared__ float slogq2[Mm];
    __shared__ float sq[Mm];
    __shared__ float sFn[Mm];
    __shared__ float sred[8 * 4];
    __shared__ float sScal[4];

    const int tid  = threadIdx.x;
    const int bid  = blockIdx.x;
    const int b    = bid >> 4;
    const int k    = bid & 15;
    const int lane = tid & 31;
    const int wid  = tid >> 5;
    const float L2E = 1.44269504088896340736f;

    const float alpha = 1.f / (1.f + expf(-a0[0]));

    // --- load C2, q softmax, features ---
    sC2[tid] = tA[k * 256 + tid];
    if (tid == 0) {
        float qv[16], mq = -1e30f;
        #pragma unroll
        for (int j = 0; j < 16; j++) { qv[j] = q0[k * 16 + j]; mq = fmaxf(mq, qv[j]); }
        float s = 0.f;
        #pragma unroll
        for (int j = 0; j < 16; j++) { qv[j] = ex2((qv[j] - mq) * L2E); s += qv[j]; }
        float inv = 1.f / s;
        #pragma unroll
        for (int j = 0; j < 16; j++) {
            float qq = qv[j] * inv;
            sq[j] = qq;
            slogq2[j] = lg2(qq);
        }
    }
    for (int t = tid; t < Mm * Dd; t += 256) sT[t] = tF[k * Mm * Dd + t];
    __syncthreads();

    if (tid < 16) {
        float s = 0.f;
        #pragma unroll
        for (int l = 0; l < 16; l++) { float c = sC2[tid * 16 + l]; s += c * c * sq[l]; }
        scc2[tid] = s;
        float fn = 0.f;
        for (int d = 0; d < Dd; d++) { float f = sT[tid * Dd + d]; fn += f * f; }
        sFn[tid] = fn;
    }

    // --- Mcost row ---
    float Mr[16];
    #pragma unroll
    for (int j = 0; j < 16; j++) Mr[j] = 0.f;
    float xn = 0.f;
    const float4* xr = (const float4*)(x + ((size_t)(b * Nn + tid)) * Dd);
    for (int d4 = 0; d4 < Dd / 4; d4++) {
        float4 xv = xr[d4];
        xn += xv.x * xv.x + xv.y * xv.y + xv.z * xv.z + xv.w * xv.w;
        #pragma unroll
        for (int j = 0; j < 16; j++) {
            float4 fv = ((const float4*)sT)[j * (Dd / 4) + d4];
            Mr[j] += xv.x * fv.x + xv.y * fv.y + xv.z * fv.z + xv.w * fv.w;
        }
    }
    __syncthreads();
    #pragma unroll
    for (int j = 0; j < 16; j++) Mr[j] = xn + sFn[j] - 2.f * Mr[j];

    const int grow = b * Nn + tid;
    const int cnt = g_cnt[grow];
    const size_t cbase = (size_t)grow * CAP;
    const float cc1 = g_cc1[grow];

    float T[16];
    #pragma unroll
    for (int j = 0; j < 16; j++) T[j] = sq[j] * (1.f / Nn);

    float CTC[16];
    const int cj = tid >> 4, cs = tid & 15;

    for (int it = 0; it <= CG_ITERS; it++) {
        // ===== CTC = C1 @ T @ C2^T =====
        {
            float4* st = (float4*)(sT + tid * STR);
            st[0] = make_float4(T[0], T[1], T[2], T[3]);
            st[1] = make_float4(T[4], T[5], T[6], T[7]);
            st[2] = make_float4(T[8], T[9], T[10], T[11]);
            st[3] = make_float4(T[12], T[13], T[14], T[15]);
        }
        __syncthreads();
        float R[16];
        spmm_row(sT, cbase, cnt, R);
        __syncthreads();
        #pragma unroll
        for (int jj = 0; jj < 16; jj++) {
            float s = 0.f;
            #pragma unroll
            for (int l4 = 0; l4 < 4; l4++) {
                float4 c4 = ((const float4*)sC2)[jj * 4 + l4];
                s += R[l4 * 4 + 0] * c4.x + R[l4 * 4 + 1] * c4.y
                   + R[l4 * 4 + 2] * c4.z + R[l4 * 4 + 3] * c4.w;
            }
            CTC[jj] = s;
        }
        if (it == CG_ITERS) break;

        // ===== gradient -> negC (log2-scaled), block max |grad| =====
        float negC[16];
        float mxa = 0.f;
        #pragma unroll
        for (int j = 0; j < 16; j++) {
            float g = (1.f - alpha) * Mr[j]
                    + 2.f * alpha * (cc1 + scc2[j] - 2.f * CTC[j]);
            negC[j] = g;
            mxa = fmaxf(mxa, fabsf(g));
        }
        #pragma unroll
        for (int o = 16; o; o >>= 1) mxa = fmaxf(mxa, __shfl_xor_sync(0xffffffffu, mxa, o));
        if (lane == 0) sred[wid] = mxa;
        __syncthreads();
        {
            float m = fmaxf(fmaxf(fmaxf(sred[0], sred[1]), fmaxf(sred[2], sred[3])),
                            fmaxf(fmaxf(sred[4], sred[5]), fmaxf(sred[6], sred[7])));
            float cscale = -L2E / (0.01f * m + 1e-12f);
            #pragma unroll
            for (int j = 0; j < 16; j++) negC[j] *= cscale;
        }

        // ===== per-row kernel Kr = 2^(negC - rmax) =====
        float rmax = negC[0];
        #pragma unroll
        for (int j = 1; j < 16; j++) rmax = fmaxf(rmax, negC[j]);
        float Kr[16];
        #pragma unroll
        for (int j = 0; j < 16; j++) Kr[j] = ex2(negC[j] - rmax);

        // ===== transpose negC; per-column kernel Kc_t = 2^(negC^T - cmax) =====
        __syncthreads();   // everyone past grad-max read of sred; sT free
        {
            float4* st = (float4*)(sT + tid * STR);
            st[0] = make_float4(negC[0], negC[1], negC[2], negC[3]);
            st[1] = make_float4(negC[4], negC[5], negC[6], negC[7]);
            st[2] = make_float4(negC[8], negC[9], negC[10], negC[11]);
            st[3] = make_float4(negC[12], negC[13], negC[14], negC[15]);
        }
        __syncthreads();
        float Kc_t[16];
        {
            float nt[16], cm = -1e30f;
            #pragma unroll
            for (int r = 0; r < 16; r++) {
                nt[r] = sT[(cs * 16 + r) * STR + cj];
                cm = fmaxf(cm, nt[r]);
            }
            #pragma unroll
            for (int o = 8; o; o >>= 1) cm = fmaxf(cm, __shfl_xor_sync(0xffffffffu, cm, o));
            #pragma unroll
            for (int r = 0; r < 16; r++) Kc_t[r] = ex2(nt[r] - cm);
            if (cs == 0) scmx[cj] = cm;
        }
        // init G = 0, vg = 1, Cf = -8
        if (tid < 16) { sG[tid] = 0.f; sVg[tid] = 1.f; }
        if (tid == 0) sScal[2] = -8.f;
        __syncthreads();

        // ===== Sinkhorn: scaled linear domain, 2 MUFU/thread/iter =====
        float F2 = 0.f;
        for (int sk = 0; sk < SINK_ITERS; sk++) {
            // --- F phase ---
            float Cf = sScal[2];
            const float4* gp = (const float4*)sVg;
            float4 v0 = gp[0], v1 = gp[1], v2 = gp[2], v3 = gp[3];
            float s0 = Kr[0]  * v0.x + Kr[1]  * v0.y + Kr[2]  * v0.z + Kr[3]  * v0.w;
            float s1 = Kr[4]  * v1.x + Kr[5]  * v1.y + Kr[6]  * v1.z + Kr[7]  * v1.w;
            float s2 = Kr[8]  * v2.x + Kr[9]  * v2.y + Kr[10] * v2.z + Kr[11] * v2.w;
            float s3 = Kr[12] * v3.x + Kr[13] * v3.y + Kr[14] * v3.z + Kr[15] * v3.w;
            float s = fmaxf((s0 + s1) + (s2 + s3), 1e-37f);
            F2 = Cf - rmax - lg2(s);
            // block max of F
            float fm = F2;
            #pragma unroll
            for (int o = 16; o; o >>= 1) fm = fmaxf(fm, __shfl_xor_sync(0xffffffffu, fm, o));
            if (lane == 0) sred[wid] = fm;
            __syncthreads();
            float fmax = fmaxf(fmaxf(fmaxf(sred[0], sred[1]), fmaxf(sred[2], sred[3])),
                               fmaxf(fmaxf(sred[4], sred[5]), fmaxf(sred[6], sred[7])));
            float uf = ex2(F2 - fmax);
            sFp[FPAD(tid)] = uf;
            __syncthreads();

            // --- G phase: colsum_j = sum_i Kc_ij * uf_i ---
            float part;
            {
                const float4* fp = (const float4*)(sFp + cs * STR);
                float4 a = fp[0], bb = fp[1], c = fp[2], d = fp[3];
                part = Kc_t[0]  * a.x  + Kc_t[1]  * a.y  + Kc_t[2]  * a.z  + Kc_t[3]  * a.w
                     + Kc_t[4]  * bb.x + Kc_t[5]  * bb.y + Kc_t[6]  * bb.z + Kc_t[7]  * bb.w
                     + Kc_t[8]  * c.x  + Kc_t[9]  * c.y  + Kc_t[10] * c.z  + Kc_t[11] * c.w
                     + Kc_t[12] * d.x  + Kc_t[13] * d.y  + Kc_t[14] * d.z  + Kc_t[15] * d.w;
            }
            #pragma unroll
            for (int o = 8; o; o >>= 1) part += __shfl_xor_sync(0xffffffffu, part, o);
            if (cs == 0) sCS[cj] = part;
            if (lane == 0) sred[wid] = fmax;   // pass fmax to tail (warp0 lane0 value ok for all)
            __syncthreads();

            // --- tail: 16 threads finish G, gmax, vg ---
            if (tid < 16) {
                float csum = fmaxf(sCS[tid], 1e-37f);
                float g = slogq2[tid] - scmx[tid] - fmax - lg2(csum);
                float gm = g;
                #pragma unroll
                for (int o = 8; o; o >>= 1) gm = fmaxf(gm, __shfl_xor_sync(0x0000ffffu, gm, o));
                sG[tid] = g;
                sVg[tid] = ex2(g - gm);
                if (tid == 0) sScal[2] = -8.f - gm;
            }
            __syncthreads();
        }

        // ===== Tnew, dT (F2 = last F, sG = last G) =====
        float dT[16];
        {
            const float4* gp = (const float4*)sG;
            float4 g0 = gp[0], g1 = gp[1], g2 = gp[2], g3 = gp[3];
            float Gv[16] = { g0.x,g0.y,g0.z,g0.w, g1.x,g1.y,g1.z,g1.w,
                             g2.x,g2.y,g2.z,g2.w, g3.x,g3.y,g3.z,g3.w };
            #pragma unroll
            for (int j = 0; j < 16; j++)
                dT[j] = ex2(negC[j] + F2 + Gv[j]) - T[j];
        }
        __syncthreads();

        // ===== D = C1 @ dT @ C2^T =====
        {
            float4* st = (float4*)(sT + tid * STR);
            st[0] = make_float4(dT[0], dT[1], dT[2], dT[3]);
            st[1] = make_float4(dT[4], dT[5], dT[6], dT[7]);
            st[2] = make_float4(dT[8], dT[9], dT[10], dT[11]);
            st[3] = make_float4(dT[12], dT[13], dT[14], dT[15]);
        }
        __syncthreads();
        float Rd[16];
        spmm_row(sT, cbase, cnt, Rd);
        __syncthreads();
        float D[16];
        #pragma unroll
        for (int jj = 0; jj < 16; jj++) {
            float s = 0.f;
            #pragma unroll
            for (int l4 = 0; l4 < 4; l4++) {
                float4 c4 = ((const float4*)sC2)[jj * 4 + l4];
                s += Rd[l4 * 4 + 0] * c4.x + Rd[l4 * 4 + 1] * c4.y
                   + Rd[l4 * 4 + 2] * c4.z + Rd[l4 * 4 + 3] * c4.w;
            }
            D[jj] = s;
        }

        // ===== line search =====
        float pa = 0.f, pb1 = 0.f, pb2 = 0.f, pb3 = 0.f;
        #pragma unroll
        for (int j = 0; j < 16; j++) {
            pa  += D[j] * dT[j];
            pb1 += Mr[j] * dT[j];
            pb2 += D[j] * T[j];
            pb3 += CTC[j] * dT[j];
        }
        #pragma unroll
        for (int o = 16; o; o >>= 1) {
            pa  += __shfl_xor_sync(0xffffffffu, pa, o);
            pb1 += __shfl_xor_sync(0xffffffffu, pb1, o);
            pb2 += __shfl_xor_sync(0xffffffffu, pb2, o);
            pb3 += __shfl_xor_sync(0xffffffffu, pb3, o);
        }
        if (lane == 0) {
            sred[wid * 4 + 0] = pa;  sred[wid * 4 + 1] = pb1;
            sred[wid * 4 + 2] = pb2; sred[wid * 4 + 3] = pb3;
        }
        __syncthreads();
        if (tid == 0) {
            float Sa = 0.f, S1 = 0.f, S2 = 0.f, S3 = 0.f;
            #pragma unroll
            for (int w = 0; w < 8; w++) {
                Sa += sred[w * 4 + 0]; S1 += sred[w * 4 + 1];
                S2 += sred[w * 4 + 2]; S3 += sred[w * 4 + 3];
            }
            float A  = -2.f * alpha * Sa;
            float Bc = (1.f - alpha) * S1 - 2.f * alpha * (S2 + S3);
            float tstep;
            if (A > 0.f) {
                tstep = -Bc / (2.f * A + 1e-16f);
                tstep = fminf(1.f, fmaxf(0.f, tstep));
            } else {
                tstep = (A + Bc < 0.f) ? 1.f : 0.f;
            }
            sScal[1] = tstep;
        }
        __syncthreads();
        float ts = sScal[1];
        #pragma unroll
        for (int j = 0; j < 16; j++) T[j] += ts * dT[j];
    }

    // ===== epilogue =====
    float pg = 0.f, pl = 0.f;
    #pragma unroll
    for (int j = 0; j < 16; j++) {
        pg += (cc1 + scc2[j] - 2.f * CTC[j]) * T[j];
        pl += Mr[j] * T[j];
    }
    #pragma unroll
    for (int o = 16; o; o >>= 1) {
        pg += __shfl_xor_sync(0xffffffffu, pg, o);
        pl += __shfl_xor_sync(0xffffffffu, pl, o);
    }
    if (lane == 0) { sred[wid * 2] = pg; sred[wid * 2 + 1] = pl; }
    __syncthreads();
    if (tid == 0) {
        float Gw = 0.f, L = 0.f;
        #pragma unroll
        for (int w = 0; w < 8; w++) { Gw += sred[w * 2]; L += sred[w * 2 + 1]; }
        out[bid] = (1.f - alpha) * L + alpha * Gw;
    }
}

// ============================ launch ============================

extern "C" void kernel_launch(void* const* d_in, const int* in_sizes, int n_in,
                              void* d_out, int out_size)
{
    const float* x  = (const float*)d_in[0];
    const int*   ei = (const int*)  d_in[1];
    const float* tA = (const float*)d_in[3];
    const float* tF = (const float*)d_in[4];
    const float* q0 = (const float*)d_in[5];
    const float* a0 = (const float*)d_in[6];
    int E = in_sizes[1] / 2;

    k_zero<<<8192, 256>>>();
    k_scatter<<<(E + 255) / 256, 256>>>(ei, E);
    k_csr<<<(Bg * Nn * 32 + 255) / 256, 256>>>();
    k_fgw<<<Bg * Kk, 256>>>(x, tA, tF, q0, a0, (float*)d_out);
}

// round 4
// speedup vs baseline: 1.5118x; 1.2439x over previous
#include <cuda_runtime.h>
#include <cstdint>
#include <cstddef>

// ---- static problem sizes (match reference) ----
#define Bg 128
#define Nn 256
#define Dd 128
#define Kk 16
#define Mm 16
#define CG_ITERS 10
#define SINK_ITERS 50
#define CAP 128
#define STR 20           // smem staging stride in floats (80B, 16B-aligned)
#define PROB (Bg * Kk)

#define FPAD(i) ((i) + 4 * ((i) >> 4))   // padded index: 16-blocks at stride 20

// ---- device scratch (no cudaMalloc anywhere) ----
__device__ float           g_C[(size_t)Bg * Nn * Nn];
__device__ float           g_val[(size_t)Bg * Nn * CAP];
__device__ unsigned short  g_col[(size_t)Bg * Nn * CAP];
__device__ int             g_cnt[Bg * Nn];
__device__ float           g_cc1[Bg * Nn];
__device__ float           g_Mr[(size_t)PROB * Nn * Mm];   // Mcost spill (per-thread)
__device__ float           g_CT[(size_t)PROB * Nn * Mm];   // CTC spill (per-thread)

// ============================ precompute ============================

__global__ void k_zero()
{
    size_t n = (size_t)Bg * Nn * Nn;
    for (size_t i = (size_t)blockIdx.x * blockDim.x + threadIdx.x; i < n;
         i += (size_t)gridDim.x * blockDim.x)
        g_C[i] = 0.f;
}

__global__ void k_scatter(const int* __restrict__ ei, int E)
{
    int e = blockIdx.x * blockDim.x + threadIdx.x;
    if (e >= E) return;
    int s = ei[e];
    int t = ei[E + e];
    int g = s >> 8;
    atomicAdd(&g_C[((size_t)(g * Nn + (s & 255))) * Nn + (t & 255)], 1.f);
}

__global__ void k_csr()
{
    int w = (blockIdx.x * blockDim.x + threadIdx.x) >> 5;
    int lane = threadIdx.x & 31;
    if (w >= Bg * Nn) return;
    const float* Crow = g_C + (size_t)w * Nn;
    float s2 = 0.f;
    int out = 0;
    size_t base = (size_t)w * CAP;
    for (int c0 = 0; c0 < Nn; c0 += 32) {
        float v = Crow[c0 + lane];
        s2 += v * v;
        unsigned m = __ballot_sync(0xffffffffu, v != 0.f);
        int off = __popc(m & ((1u << lane) - 1u));
        if (v != 0.f && (out + off) < CAP) {
            g_val[base + out + off] = v;
            g_col[base + out + off] = (unsigned short)(c0 + lane);
        }
        out += __popc(m);
    }
    #pragma unroll
    for (int o = 16; o; o >>= 1) s2 += __shfl_xor_sync(0xffffffffu, s2, o);
    if (lane == 0) {
        g_cnt[w] = out > CAP ? CAP : out;
        g_cc1[w] = s2 * (1.f / Nn);
    }
}

// ============================ main kernel ============================

__device__ __forceinline__ float ex2(float x)
{
    float r; asm("ex2.approx.ftz.f32 %0, %1;" : "=f"(r) : "f"(x)); return r;
}
__device__ __forceinline__ float lg2(float x)
{
    float r; asm("lg2.approx.ftz.f32 %0, %1;" : "=f"(r) : "f"(x)); return r;
}
__device__ __forceinline__ float rcpa(float x)
{
    float r; asm("rcp.approx.ftz.f32 %0, %1;" : "=f"(r) : "f"(x)); return r;
}

__device__ __forceinline__ void spmm_row(const float* sT, size_t cbase, int cnt,
                                         float R[16])
{
    #pragma unroll
    for (int j = 0; j < 16; j++) R[j] = 0.f;
    for (int e = 0; e < cnt; e++) {
        int   c  = g_col[cbase + e];
        float vv = g_val[cbase + e];
        const float4* tp = (const float4*)(sT + c * STR);
        float4 t0 = tp[0], t1 = tp[1], t2 = tp[2], t3 = tp[3];
        R[0]  += vv * t0.x; R[1]  += vv * t0.y; R[2]  += vv * t0.z; R[3]  += vv * t0.w;
        R[4]  += vv * t1.x; R[5]  += vv * t1.y; R[6]  += vv * t1.z; R[7]  += vv * t1.w;
        R[8]  += vv * t2.x; R[9]  += vv * t2.y; R[10] += vv * t2.z; R[11] += vv * t2.w;
        R[12] += vv * t3.x; R[13] += vv * t3.y; R[14] += vv * t3.z; R[15] += vv * t3.w;
    }
}

__global__ __launch_bounds__(256, 3)
void k_fgw(const float* __restrict__ x,
           const float* __restrict__ tA,
           const float* __restrict__ tF,
           const float* __restrict__ q0,
           const float* __restrict__ a0,
           float* __restrict__ out)
{
    __shared__ __align__(16) float sT[Nn * STR];       // staging (20KB)
    __shared__ __align__(16) float sU[Nn + Nn / 4];    // padded u buffer
    __shared__ __align__(16) float sW[Mm];             // scaled v (== 2^G exactly)
    __shared__ __align__(16) float sCS[Mm];            // column sums S_j
    __shared__ __align__(16) float scmx[Mm];           // cmax_j
    __shared__ __align__(16) float sqCW[Mm];           // q_j * CW_j
    __shared__ __align__(16) float sLC[Mm];            // logq2 - lg2 S - cmax
    __shared__ __align__(16) float sC2[Mm * Mm];
    __shared__ float scc2[Mm];
    __shared__ float slogq2[Mm];
    __shared__ float sq[Mm];
    __shared__ float sFn[Mm];
    __shared__ float sred[32];
    __shared__ float sScal[4];

    const int tid  = threadIdx.x;
    const int bid  = blockIdx.x;
    const int b    = bid >> 4;
    const int k    = bid & 15;
    const int lane = tid & 31;
    const int wid  = tid >> 5;
    const float L2E = 1.44269504088896340736f;

    const float alpha = 1.f / (1.f + expf(-a0[0]));
    const size_t sbase = ((size_t)bid * Nn + tid) * Mm;   // spill base

    // --- load C2, q softmax, features ---
    sC2[tid] = tA[k * 256 + tid];
    if (tid == 0) {
        float qv[16], mq = -1e30f;
        #pragma unroll
        for (int j = 0; j < 16; j++) { qv[j] = q0[k * 16 + j]; mq = fmaxf(mq, qv[j]); }
        float s = 0.f;
        #pragma unroll
        for (int j = 0; j < 16; j++) { qv[j] = ex2((qv[j] - mq) * L2E); s += qv[j]; }
        float inv = 1.f / s;
        #pragma unroll
        for (int j = 0; j < 16; j++) {
            float qq = qv[j] * inv;
            sq[j] = qq;
            slogq2[j] = lg2(qq);
        }
    }
    for (int t = tid; t < Mm * Dd; t += 256) sT[t] = tF[k * Mm * Dd + t];
    __syncthreads();

    if (tid < 16) {
        float s = 0.f;
        #pragma unroll
        for (int l = 0; l < 16; l++) { float c = sC2[tid * 16 + l]; s += c * c * sq[l]; }
        scc2[tid] = s;
        float fn = 0.f;
        for (int d = 0; d < Dd; d++) { float f = sT[tid * Dd + d]; fn += f * f; }
        sFn[tid] = fn;
    }

    // --- Mcost row -> spill to g_Mr ---
    {
        float Mr[16];
        #pragma unroll
        for (int j = 0; j < 16; j++) Mr[j] = 0.f;
        float xn = 0.f;
        const float4* xr = (const float4*)(x + ((size_t)(b * Nn + tid)) * Dd);
        for (int d4 = 0; d4 < Dd / 4; d4++) {
            float4 xv = xr[d4];
            xn += xv.x * xv.x + xv.y * xv.y + xv.z * xv.z + xv.w * xv.w;
            #pragma unroll
            for (int j = 0; j < 16; j++) {
                float4 fv = ((const float4*)sT)[j * (Dd / 4) + d4];
                Mr[j] += xv.x * fv.x + xv.y * fv.y + xv.z * fv.z + xv.w * fv.w;
            }
        }
        __syncthreads();   // sFn ready; feature reads done
        float4* mp = (float4*)(g_Mr + sbase);
        #pragma unroll
        for (int j4 = 0; j4 < 4; j4++) {
            float4 v;
            v.x = xn + sFn[j4 * 4 + 0] - 2.f * Mr[j4 * 4 + 0];
            v.y = xn + sFn[j4 * 4 + 1] - 2.f * Mr[j4 * 4 + 1];
            v.z = xn + sFn[j4 * 4 + 2] - 2.f * Mr[j4 * 4 + 2];
            v.w = xn + sFn[j4 * 4 + 3] - 2.f * Mr[j4 * 4 + 3];
            mp[j4] = v;
        }
    }

    const int grow = b * Nn + tid;
    const int cnt = g_cnt[grow];
    const size_t cbase = (size_t)grow * CAP;
    const float cc1 = g_cc1[grow];

    float T[16];
    #pragma unroll
    for (int j = 0; j < 16; j++) T[j] = sq[j] * (1.f / Nn);

    float CTC[16];
    const int cj = tid >> 4, cs = tid & 15;

    for (int it = 0; it <= CG_ITERS; it++) {
        // ===== A: CTC = C1 @ T @ C2^T =====
        {
            float4* st = (float4*)(sT + tid * STR);
            st[0] = make_float4(T[0], T[1], T[2], T[3]);
            st[1] = make_float4(T[4], T[5], T[6], T[7]);
            st[2] = make_float4(T[8], T[9], T[10], T[11]);
            st[3] = make_float4(T[12], T[13], T[14], T[15]);
        }
        __syncthreads();
        float R[16];
        spmm_row(sT, cbase, cnt, R);
        #pragma unroll
        for (int jj = 0; jj < 16; jj++) {
            float s = 0.f;
            #pragma unroll
            for (int l4 = 0; l4 < 4; l4++) {
                float4 c4 = ((const float4*)sC2)[jj * 4 + l4];
                s += R[l4 * 4 + 0] * c4.x + R[l4 * 4 + 1] * c4.y
                   + R[l4 * 4 + 2] * c4.z + R[l4 * 4 + 3] * c4.w;
            }
            CTC[jj] = s;
        }
        if (it == CG_ITERS) break;

        // ===== B: gradient, spill CTC, block reductions (maxabs, maxgmin) =====
        float negC[16];
        float mxa = 0.f, gmn = 1e30f;
        {
            const float4* mp = (const float4*)(g_Mr + sbase);
            float4* cp = (float4*)(g_CT + sbase);
            #pragma unroll
            for (int j4 = 0; j4 < 4; j4++) {
                float4 mv = mp[j4];
                float m0 = mv.x, m1 = mv.y, m2 = mv.z, m3 = mv.w;
                float g0 = (1.f - alpha) * m0 + 2.f * alpha * (cc1 + scc2[j4*4+0] - 2.f * CTC[j4*4+0]);
                float g1 = (1.f - alpha) * m1 + 2.f * alpha * (cc1 + scc2[j4*4+1] - 2.f * CTC[j4*4+1]);
                float g2 = (1.f - alpha) * m2 + 2.f * alpha * (cc1 + scc2[j4*4+2] - 2.f * CTC[j4*4+2]);
                float g3 = (1.f - alpha) * m3 + 2.f * alpha * (cc1 + scc2[j4*4+3] - 2.f * CTC[j4*4+3]);
                negC[j4*4+0] = g0; negC[j4*4+1] = g1; negC[j4*4+2] = g2; negC[j4*4+3] = g3;
                mxa = fmaxf(mxa, fmaxf(fmaxf(fabsf(g0), fabsf(g1)), fmaxf(fabsf(g2), fabsf(g3))));
                gmn = fminf(gmn, fminf(fminf(g0, g1), fminf(g2, g3)));
                cp[j4] = make_float4(CTC[j4*4+0], CTC[j4*4+1], CTC[j4*4+2], CTC[j4*4+3]);
            }
        }
        #pragma unroll
        for (int o = 16; o; o >>= 1) {
            mxa = fmaxf(mxa, __shfl_xor_sync(0xffffffffu, mxa, o));
            gmn = fmaxf(gmn, __shfl_xor_sync(0xffffffffu, gmn, o));   // max_i of per-row min
        }
        if (lane == 0) { sred[wid] = mxa; sred[16 + wid] = gmn; }
        __syncthreads();
        float cscale, rho;
        {
            float m = fmaxf(fmaxf(fmaxf(sred[0], sred[1]), fmaxf(sred[2], sred[3])),
                            fmaxf(fmaxf(sred[4], sred[5]), fmaxf(sred[6], sred[7])));
            float mg = fmaxf(fmaxf(fmaxf(sred[16], sred[17]), fmaxf(sred[18], sred[19])),
                             fmaxf(fmaxf(sred[20], sred[21]), fmaxf(sred[22], sred[23])));
            cscale = -L2E / (0.01f * m + 1e-12f);
            rho = 0.5f * (cscale * mg);    // mrm/2 ; mrm = min_i rmax_i = cscale * max_i gmin_i
        }
        float rmax = -1e30f;
        #pragma unroll
        for (int j = 0; j < 16; j++) { negC[j] *= cscale; rmax = fmaxf(rmax, negC[j]); }
        float Kr[16];
        #pragma unroll
        for (int j = 0; j < 16; j++) Kr[j] = ex2(negC[j] - rmax);
        float Ri = ex2(rho - rmax);

        // ===== C: transpose, column kernels =====
        {
            float4* st = (float4*)(sT + tid * STR);
            st[0] = make_float4(negC[0], negC[1], negC[2], negC[3]);
            st[1] = make_float4(negC[4], negC[5], negC[6], negC[7]);
            st[2] = make_float4(negC[8], negC[9], negC[10], negC[11]);
            st[3] = make_float4(negC[12], negC[13], negC[14], negC[15]);
        }
        __syncthreads();
        float Kc_t[16];
        {
            float nt[16], cm = -1e30f;
            #pragma unroll
            for (int r = 0; r < 16; r++) {
                nt[r] = sT[(cs * 16 + r) * STR + cj];
                cm = fmaxf(cm, nt[r]);
            }
            #pragma unroll
            for (int o = 8; o; o >>= 1) cm = fmaxf(cm, __shfl_xor_sync(0xffffffffu, cm, o));
            #pragma unroll
            for (int r = 0; r < 16; r++) Kc_t[r] = ex2(nt[r] - cm);
            if (cs == 0) {
                scmx[cj] = cm;
                sqCW[cj] = sq[cj] * ex2(rho + 8.f - cm);
                sW[cj]   = 1.f;
            }
        }
        __syncthreads();

        // ===== D: Sinkhorn, linear domain, 2 barriers + 2 RCP per iter =====
        float U = 0.f;
        for (int sk = 0; sk < SINK_ITERS; sk++) {
            // row: u = Ri / (Kr . W)
            {
                const float4* wp = (const float4*)sW;
                float4 w0 = wp[0], w1 = wp[1], w2 = wp[2], w3 = wp[3];
                float s0 = Kr[0]  * w0.x + Kr[1]  * w0.y + Kr[2]  * w0.z + Kr[3]  * w0.w;
                float s1 = Kr[4]  * w1.x + Kr[5]  * w1.y + Kr[6]  * w1.z + Kr[7]  * w1.w;
                float s2 = Kr[8]  * w2.x + Kr[9]  * w2.y + Kr[10] * w2.z + Kr[11] * w2.w;
                float s3 = Kr[12] * w3.x + Kr[13] * w3.y + Kr[14] * w3.z + Kr[15] * w3.w;
                float s = fmaxf((s0 + s1) + (s2 + s3), 1e-37f);
                U = Ri * rcpa(s);
                sU[FPAD(tid)] = U;
            }
            __syncthreads();
            // col: S_j = Kc^T . u ; W_j = q_j*CW_j / S_j
            {
                const float4* up = (const float4*)(sU + cs * STR);
                float4 a = up[0], bb = up[1], c = up[2], d = up[3];
                float S = Kc_t[0]  * a.x  + Kc_t[1]  * a.y  + Kc_t[2]  * a.z  + Kc_t[3]  * a.w
                        + Kc_t[4]  * bb.x + Kc_t[5]  * bb.y + Kc_t[6]  * bb.z + Kc_t[7]  * bb.w
                        + Kc_t[8]  * c.x  + Kc_t[9]  * c.y  + Kc_t[10] * c.z  + Kc_t[11] * c.w
                        + Kc_t[12] * d.x  + Kc_t[13] * d.y  + Kc_t[14] * d.z  + Kc_t[15] * d.w;
                #pragma unroll
                for (int o = 8; o; o >>= 1) S += __shfl_xor_sync(0xffffffffu, S, o);
                S = fmaxf(S, 1e-37f);
                if (cs == 0) { sCS[cj] = S; sW[cj] = sqCW[cj] * rcpa(S); }
            }
            __syncthreads();
        }

        // ===== E: per-column log factors for exact plan recovery =====
        if (tid < 16)
            sLC[tid] = slogq2[tid] - lg2(sCS[tid]) - scmx[tid];
        __syncthreads();

        // ===== F: Tnew_ij = 2^( lg2 Kr + rmax + lg2 U + sLC_j ), dT =====
        float dT[16];
        {
            float lu = lg2(U) + rmax;
            const float4* lp = (const float4*)sLC;
            float4 l0 = lp[0], l1 = lp[1], l2 = lp[2], l3 = lp[3];
            float Lv[16] = { l0.x,l0.y,l0.z,l0.w, l1.x,l1.y,l1.z,l1.w,
                             l2.x,l2.y,l2.z,l2.w, l3.x,l3.y,l3.z,l3.w };
            #pragma unroll
            for (int j = 0; j < 16; j++)
                dT[j] = ex2(lg2(Kr[j]) + lu + Lv[j]) - T[j];
        }

        // ===== G: D = C1 @ dT @ C2^T =====
        {
            float4* st = (float4*)(sT + tid * STR);
            st[0] = make_float4(dT[0], dT[1], dT[2], dT[3]);
            st[1] = make_float4(dT[4], dT[5], dT[6], dT[7]);
            st[2] = make_float4(dT[8], dT[9], dT[10], dT[11]);
            st[3] = make_float4(dT[12], dT[13], dT[14], dT[15]);
        }
        __syncthreads();
        float Rd[16];
        spmm_row(sT, cbase, cnt, Rd);
        float D[16];
        #pragma unroll
        for (int jj = 0; jj < 16; jj++) {
            float s = 0.f;
            #pragma unroll
            for (int l4 = 0; l4 < 4; l4++) {
                float4 c4 = ((const float4*)sC2)[jj * 4 + l4];
                s += Rd[l4 * 4 + 0] * c4.x + Rd[l4 * 4 + 1] * c4.y
                   + Rd[l4 * 4 + 2] * c4.z + Rd[l4 * 4 + 3] * c4.w;
            }
            D[jj] = s;
        }

        // ===== H: line search =====
        float pa = 0.f, pb1 = 0.f, pb2 = 0.f, pb3 = 0.f;
        {
            const float4* mp = (const float4*)(g_Mr + sbase);
            const float4* cp = (const float4*)(g_CT + sbase);
            #pragma unroll
            for (int j4 = 0; j4 < 4; j4++) {
                float4 mv = mp[j4];
                float4 cv = cp[j4];
                pa  += D[j4*4+0] * dT[j4*4+0] + D[j4*4+1] * dT[j4*4+1]
                     + D[j4*4+2] * dT[j4*4+2] + D[j4*4+3] * dT[j4*4+3];
                pb1 += mv.x * dT[j4*4+0] + mv.y * dT[j4*4+1]
                     + mv.z * dT[j4*4+2] + mv.w * dT[j4*4+3];
                pb2 += D[j4*4+0] * T[j4*4+0] + D[j4*4+1] * T[j4*4+1]
                     + D[j4*4+2] * T[j4*4+2] + D[j4*4+3] * T[j4*4+3];
                pb3 += cv.x * dT[j4*4+0] + cv.y * dT[j4*4+1]
                     + cv.z * dT[j4*4+2] + cv.w * dT[j4*4+3];
            }
        }
        #pragma unroll
        for (int o = 16; o; o >>= 1) {
            pa  += __shfl_xor_sync(0xffffffffu, pa, o);
            pb1 += __shfl_xor_sync(0xffffffffu, pb1, o);
            pb2 += __shfl_xor_sync(0xffffffffu, pb2, o);
            pb3 += __shfl_xor_sync(0xffffffffu, pb3, o);
        }
        if (lane == 0) {
            sred[wid * 4 + 0] = pa;  sred[wid * 4 + 1] = pb1;
            sred[wid * 4 + 2] = pb2; sred[wid * 4 + 3] = pb3;
        }
        __syncthreads();
        if (tid == 0) {
            float Sa = 0.f, S1 = 0.f, S2 = 0.f, S3 = 0.f;
            #pragma unroll
            for (int w = 0; w < 8; w++) {
                Sa += sred[w * 4 + 0]; S1 += sred[w * 4 + 1];
                S2 += sred[w * 4 + 2]; S3 += sred[w * 4 + 3];
            }
            float A  = -2.f * alpha * Sa;
            float Bc = (1.f - alpha) * S1 - 2.f * alpha * (S2 + S3);
            float tstep;
            if (A > 0.f) {
                tstep = -Bc / (2.f * A + 1e-16f);
                tstep = fminf(1.f, fmaxf(0.f, tstep));
            } else {
                tstep = (A + Bc < 0.f) ? 1.f : 0.f;
            }
            sScal[1] = tstep;
        }
        __syncthreads();
        float ts = sScal[1];
        #pragma unroll
        for (int j = 0; j < 16; j++) T[j] += ts * dT[j];
    }

    // ===== epilogue (CTC in regs from final A-phase) =====
    float pg = 0.f, pl = 0.f;
    {
        const float4* mp = (const float4*)(g_Mr + sbase);
        #pragma unroll
        for (int j4 = 0; j4 < 4; j4++) {
            float4 mv = mp[j4];
            pg += (cc1 + scc2[j4*4+0] - 2.f * CTC[j4*4+0]) * T[j4*4+0]
                + (cc1 + scc2[j4*4+1] - 2.f * CTC[j4*4+1]) * T[j4*4+1]
                + (cc1 + scc2[j4*4+2] - 2.f * CTC[j4*4+2]) * T[j4*4+2]
                + (cc1 + scc2[j4*4+3] - 2.f * CTC[j4*4+3]) * T[j4*4+3];
            pl += mv.x * T[j4*4+0] + mv.y * T[j4*4+1]
                + mv.z * T[j4*4+2] + mv.w * T[j4*4+3];
        }
    }
    #pragma unroll
    for (int o = 16; o; o >>= 1) {
        pg += __shfl_xor_sync(0xffffffffu, pg, o);
        pl += __shfl_xor_sync(0xffffffffu, pl, o);
    }
    if (lane == 0) { sred[wid * 2] = pg; sred[wid * 2 + 1] = pl; }
    __syncthreads();
    if (tid == 0) {
        float Gw = 0.f, L = 0.f;
        #pragma unroll
        for (int w = 0; w < 8; w++) { Gw += sred[w * 2]; L += sred[w * 2 + 1]; }
        out[bid] = (1.f - alpha) * L + alpha * Gw;
    }
}

// ============================ launch ============================

extern "C" void kernel_launch(void* const* d_in, const int* in_sizes, int n_in,
                              void* d_out, int out_size)
{
    const float* x  = (const float*)d_in[0];
    const int*   ei = (const int*)  d_in[1];
    const float* tA = (const float*)d_in[3];
    const float* tF = (const float*)d_in[4];
    const float* q0 = (const float*)d_in[5];
    const float* a0 = (const float*)d_in[6];
    int E = in_sizes[1] / 2;

    k_zero<<<8192, 256>>>();
    k_scatter<<<(E + 255) / 256, 256>>>(ei, E);
    k_csr<<<(Bg * Nn * 32 + 255) / 256, 256>>>();
    k_fgw<<<Bg * Kk, 256>>>(x, tA, tF, q0, a0, (float*)d_out);
}

// round 5
// speedup vs baseline: 2.3757x; 1.5714x over previous
#include <cuda_runtime.h>
#include <cstdint>
#include <cstddef>

// ---- static problem sizes (match reference) ----
#define Bg 128
#define Nn 256
#define Dd 128
#define Kk 16
#define Mm 16
#define CG_ITERS 10
#define SINK_ITERS 50
#define CAP 128
#define STR 20           // smem staging stride in floats (80B, 16B-aligned)
#define PROB (Bg * Kk)

#define FPAD(i) ((i) + 4 * ((i) >> 4))   // padded index: 16-blocks at stride 20

// ---- device scratch (no cudaMalloc anywhere) ----
__device__ float           g_C[(size_t)Bg * Nn * Nn];
__device__ float           g_val[(size_t)Bg * CAP * Nn];   // ELL TRANSPOSED: [b][e][row]
__device__ unsigned short  g_col[(size_t)Bg * CAP * Nn];   // [b][e][row]
__device__ int             g_cnt[Bg * Nn];
__device__ float           g_cc1[Bg * Nn];
__device__ float           g_Mr[(size_t)PROB * Nn * Mm];   // Mcost spill (per-thread)
__device__ float           g_CT[(size_t)PROB * Nn * Mm];   // CTC spill (per-thread)

// ============================ precompute ============================

__global__ void k_zero()
{
    size_t n = (size_t)Bg * Nn * Nn;
    for (size_t i = (size_t)blockIdx.x * blockDim.x + threadIdx.x; i < n;
         i += (size_t)gridDim.x * blockDim.x)
        g_C[i] = 0.f;
}

__global__ void k_scatter(const int* __restrict__ ei, int E)
{
    int e = blockIdx.x * blockDim.x + threadIdx.x;
    if (e >= E) return;
    int s = ei[e];
    int t = ei[E + e];
    int g = s >> 8;
    atomicAdd(&g_C[((size_t)(g * Nn + (s & 255))) * Nn + (t & 255)], 1.f);
}

// one warp per row: ballot-compaction into TRANSPOSED ELL [b][e][row]
__global__ void k_csr()
{
    int w = (blockIdx.x * blockDim.x + threadIdx.x) >> 5;
    int lane = threadIdx.x & 31;
    if (w >= Bg * Nn) return;
    int b = w >> 8, row = w & 255;
    const float* Crow = g_C + (size_t)w * Nn;
    float s2 = 0.f;
    int out = 0;
    size_t base = (size_t)b * CAP * Nn + row;
    for (int c0 = 0; c0 < Nn; c0 += 32) {
        float v = Crow[c0 + lane];
        s2 += v * v;
        unsigned m = __ballot_sync(0xffffffffu, v != 0.f);
        int off = __popc(m & ((1u << lane) - 1u));
        if (v != 0.f && (out + off) < CAP) {
            g_val[base + (size_t)(out + off) * Nn] = v;
            g_col[base + (size_t)(out + off) * Nn] = (unsigned short)(c0 + lane);
        }
        out += __popc(m);
    }
    #pragma unroll
    for (int o = 16; o; o >>= 1) s2 += __shfl_xor_sync(0xffffffffu, s2, o);
    if (lane == 0) {
        g_cnt[w] = out > CAP ? CAP : out;
        g_cc1[w] = s2 * (1.f / Nn);
    }
}

// ============================ main kernel ============================

__device__ __forceinline__ float ex2(float x)
{
    float r; asm("ex2.approx.ftz.f32 %0, %1;" : "=f"(r) : "f"(x)); return r;
}
__device__ __forceinline__ float lg2(float x)
{
    float r; asm("lg2.approx.ftz.f32 %0, %1;" : "=f"(r) : "f"(x)); return r;
}
__device__ __forceinline__ float rcpa(float x)
{
    float r; asm("rcp.approx.ftz.f32 %0, %1;" : "=f"(r) : "f"(x)); return r;
}

// sparse row gather with coalesced ELL loads: R = sum_e val[e][tid] * Tstage[col[e][tid]][:]
__device__ __forceinline__ void spmm_row(const float* sT, size_t ebase, int cnt,
                                         int tid, float R[16])
{
    #pragma unroll
    for (int j = 0; j < 16; j++) R[j] = 0.f;
    size_t idx = ebase + tid;
    for (int e = 0; e < cnt; e++, idx += Nn) {
        int   c  = g_col[idx];
        float vv = g_val[idx];
        const float4* tp = (const float4*)(sT + c * STR);
        float4 t0 = tp[0], t1 = tp[1], t2 = tp[2], t3 = tp[3];
        R[0]  += vv * t0.x; R[1]  += vv * t0.y; R[2]  += vv * t0.z; R[3]  += vv * t0.w;
        R[4]  += vv * t1.x; R[5]  += vv * t1.y; R[6]  += vv * t1.z; R[7]  += vv * t1.w;
        R[8]  += vv * t2.x; R[9]  += vv * t2.y; R[10] += vv * t2.z; R[11] += vv * t2.w;
        R[12] += vv * t3.x; R[13] += vv * t3.y; R[14] += vv * t3.z; R[15] += vv * t3.w;
    }
}

__global__ __launch_bounds__(256, 3)
void k_fgw(const float* __restrict__ x,
           const float* __restrict__ tA,
           const float* __restrict__ tF,
           const float* __restrict__ q0,
           const float* __restrict__ a0,
           float* __restrict__ out)
{
    __shared__ __align__(16) float sT[Nn * STR];       // staging (Kr / T / dT / features)
    __shared__ __align__(16) float sU[Nn + Nn / 4];    // padded u buffer
    __shared__ __align__(16) float sW[Mm];             // scaled v
    __shared__ __align__(16) float sPart[8 * Mm];      // per-warp column partials
    __shared__ __align__(16) float sC2[Mm * Mm];
    __shared__ float scc2[Mm];
    __shared__ float sq256[Mm];                        // 256 * q_j
    __shared__ float sq[Mm];
    __shared__ float sFn[Mm];
    __shared__ float sred[8];
    __shared__ float sScal[4];

    const int tid  = threadIdx.x;
    const int bid  = blockIdx.x;
    const int b    = bid >> 4;
    const int k    = bid & 15;
    const int lane = tid & 31;
    const int wid  = tid >> 5;
    const float L2E = 1.44269504088896340736f;

    const float alpha = 1.f / (1.f + expf(-a0[0]));
    const size_t sbase = ((size_t)bid * Nn + tid) * Mm;       // spill base
    const size_t ebase = (size_t)b * CAP * Nn;                // ELL base

    // --- load C2, q softmax, features ---
    sC2[tid] = tA[k * 256 + tid];
    if (tid == 0) {
        float qv[16], mq = -1e30f;
        #pragma unroll
        for (int j = 0; j < 16; j++) { qv[j] = q0[k * 16 + j]; mq = fmaxf(mq, qv[j]); }
        float s = 0.f;
        #pragma unroll
        for (int j = 0; j < 16; j++) { qv[j] = ex2((qv[j] - mq) * L2E); s += qv[j]; }
        float inv = 1.f / s;
        #pragma unroll
        for (int j = 0; j < 16; j++) {
            float qq = qv[j] * inv;
            sq[j] = qq;
            sq256[j] = 256.f * qq;
        }
    }
    for (int t = tid; t < Mm * Dd; t += 256) sT[t] = tF[k * Mm * Dd + t];
    __syncthreads();

    if (tid < 16) {
        float s = 0.f;
        #pragma unroll
        for (int l = 0; l < 16; l++) { float c = sC2[tid * 16 + l]; s += c * c * sq[l]; }
        scc2[tid] = s;
        float fn = 0.f;
        for (int d = 0; d < Dd; d++) { float f = sT[tid * Dd + d]; fn += f * f; }
        sFn[tid] = fn;
    }

    // --- Mcost row -> spill to g_Mr ---
    {
        float Mr[16];
        #pragma unroll
        for (int j = 0; j < 16; j++) Mr[j] = 0.f;
        float xn = 0.f;
        const float4* xr = (const float4*)(x + ((size_t)(b * Nn + tid)) * Dd);
        for (int d4 = 0; d4 < Dd / 4; d4++) {
            float4 xv = xr[d4];
            xn += xv.x * xv.x + xv.y * xv.y + xv.z * xv.z + xv.w * xv.w;
            #pragma unroll
            for (int j = 0; j < 16; j++) {
                float4 fv = ((const float4*)sT)[j * (Dd / 4) + d4];
                Mr[j] += xv.x * fv.x + xv.y * fv.y + xv.z * fv.z + xv.w * fv.w;
            }
        }
        __syncthreads();
        float4* mp = (float4*)(g_Mr + sbase);
        #pragma unroll
        for (int j4 = 0; j4 < 4; j4++) {
            float4 v;
            v.x = xn + sFn[j4 * 4 + 0] - 2.f * Mr[j4 * 4 + 0];
            v.y = xn + sFn[j4 * 4 + 1] - 2.f * Mr[j4 * 4 + 1];
            v.z = xn + sFn[j4 * 4 + 2] - 2.f * Mr[j4 * 4 + 2];
            v.w = xn + sFn[j4 * 4 + 3] - 2.f * Mr[j4 * 4 + 3];
            mp[j4] = v;
        }
    }

    const int grow = b * Nn + tid;
    const int cnt = g_cnt[grow];
    const float cc1 = g_cc1[grow];

    float T[16];
    #pragma unroll
    for (int j = 0; j < 16; j++) T[j] = sq[j] * (1.f / Nn);

    float CTC[16];
    const int cs2 = tid >> 4;        // col thread: 16-row block index
    const int cj2 = tid & 15;        // col thread: column

    for (int it = 0; it <= CG_ITERS; it++) {
        // ===== A: CTC = C1 @ T @ C2^T =====
        {
            float4* st = (float4*)(sT + tid * STR);
            st[0] = make_float4(T[0], T[1], T[2], T[3]);
            st[1] = make_float4(T[4], T[5], T[6], T[7]);
            st[2] = make_float4(T[8], T[9], T[10], T[11]);
            st[3] = make_float4(T[12], T[13], T[14], T[15]);
        }
        __syncthreads();
        float R[16];
        spmm_row(sT, ebase, cnt, tid, R);
        #pragma unroll
        for (int jj = 0; jj < 16; jj++) {
            float s = 0.f;
            #pragma unroll
            for (int l4 = 0; l4 < 4; l4++) {
                float4 c4 = ((const float4*)sC2)[jj * 4 + l4];
                s += R[l4 * 4 + 0] * c4.x + R[l4 * 4 + 1] * c4.y
                   + R[l4 * 4 + 2] * c4.z + R[l4 * 4 + 3] * c4.w;
            }
            CTC[jj] = s;
        }
        if (it == CG_ITERS) break;

        // ===== B: gradient -> Kr, spill CTC, block max|grad| =====
        float Kr[16];
        float mxa = 0.f;
        {
            const float4* mp = (const float4*)(g_Mr + sbase);
            float4* cp = (float4*)(g_CT + sbase);
            #pragma unroll
            for (int j = 0; j < 16; j++) {
                float m = ((const float*)(g_Mr + sbase))[j];
                float g = (1.f - alpha) * m + 2.f * alpha * (cc1 + scc2[j] - 2.f * CTC[j]);
                Kr[j] = g;                        // temporarily holds grad
                mxa = fmaxf(mxa, fabsf(g));
            }
            (void)mp;
            #pragma unroll
            for (int j4 = 0; j4 < 4; j4++)
                cp[j4] = make_float4(CTC[j4*4+0], CTC[j4*4+1], CTC[j4*4+2], CTC[j4*4+3]);
        }
        #pragma unroll
        for (int o = 16; o; o >>= 1) mxa = fmaxf(mxa, __shfl_xor_sync(0xffffffffu, mxa, o));
        if (lane == 0) sred[wid] = mxa;
        __syncthreads();
        {
            float m = fmaxf(fmaxf(fmaxf(sred[0], sred[1]), fmaxf(sred[2], sred[3])),
                            fmaxf(fmaxf(sred[4], sred[5]), fmaxf(sred[6], sred[7])));
            float cscale = -L2E / (0.01f * m + 1e-12f);
            float rmax = -1e30f;
            #pragma unroll
            for (int j = 0; j < 16; j++) { Kr[j] *= cscale; rmax = fmaxf(rmax, Kr[j]); }
            #pragma unroll
            for (int j = 0; j < 16; j++) Kr[j] = ex2(Kr[j] - rmax);   // Kr in (0,1]
        }
        __syncthreads();   // sred read done; sT free

        // ===== C: stage Kr, read transposed copy (Kc_t) =====
        {
            float4* st = (float4*)(sT + tid * STR);
            st[0] = make_float4(Kr[0], Kr[1], Kr[2], Kr[3]);
            st[1] = make_float4(Kr[4], Kr[5], Kr[6], Kr[7]);
            st[2] = make_float4(Kr[8], Kr[9], Kr[10], Kr[11]);
            st[3] = make_float4(Kr[12], Kr[13], Kr[14], Kr[15]);
        }
        if (tid < 16) sW[tid] = 1.f;
        __syncthreads();
        float Kc_t[16];
        #pragma unroll
        for (int r = 0; r < 16; r++)
            Kc_t[r] = sT[(cs2 * 16 + r) * STR + cj2];
        // no barrier needed: sT not rewritten until after sink loop

        // ===== D: Sinkhorn, scale-free linear domain =====
        float U = 0.f;
        for (int sk = 0; sk < SINK_ITERS; sk++) {
            // row: u = 1 / (Kr . W)
            {
                const float4* wp = (const float4*)sW;
                float4 w0 = wp[0], w1 = wp[1], w2 = wp[2], w3 = wp[3];
                float s0 = Kr[0]  * w0.x + Kr[1]  * w0.y + Kr[2]  * w0.z + Kr[3]  * w0.w;
                float s1 = Kr[4]  * w1.x + Kr[5]  * w1.y + Kr[6]  * w1.z + Kr[7]  * w1.w;
                float s2 = Kr[8]  * w2.x + Kr[9]  * w2.y + Kr[10] * w2.z + Kr[11] * w2.w;
                float s3 = Kr[12] * w3.x + Kr[13] * w3.y + Kr[14] * w3.z + Kr[15] * w3.w;
                float s = fmaxf((s0 + s1) + (s2 + s3), 1e-30f);
                U = rcpa(s);
                sU[FPAD(tid)] = U;
            }
            __syncthreads();
            // col: partial_{cj2} = sum over 16 rows of block cs2
            {
                const float4* up = (const float4*)(sU + cs2 * STR);
                float4 a = up[0], bb = up[1], c = up[2], d = up[3];
                float part = Kc_t[0]  * a.x  + Kc_t[1]  * a.y  + Kc_t[2]  * a.z  + Kc_t[3]  * a.w
                           + Kc_t[4]  * bb.x + Kc_t[5]  * bb.y + Kc_t[6]  * bb.z + Kc_t[7]  * bb.w
                           + Kc_t[8]  * c.x  + Kc_t[9]  * c.y  + Kc_t[10] * c.z  + Kc_t[11] * c.w
                           + Kc_t[12] * d.x  + Kc_t[13] * d.y  + Kc_t[14] * d.z  + Kc_t[15] * d.w;
                part += __shfl_xor_sync(0xffffffffu, part, 16);   // pair cs2 blocks in warp
                if (lane < 16) sPart[wid * 16 + lane] = part;
            }
            __syncthreads();
            // tail: P_j over 8 warps, W_j = 256 q_j / P_j
            if (tid < 16) {
                float P = sPart[tid] + sPart[16 + tid] + sPart[32 + tid] + sPart[48 + tid]
                        + sPart[64 + tid] + sPart[80 + tid] + sPart[96 + tid] + sPart[112 + tid];
                sW[tid] = sq256[tid] * rcpa(fmaxf(P, 1e-30f));
            }
            __syncthreads();
        }

        // ===== E: Tnew = (1/256) * U * Kr * W ; dT =====
        float dT[16];
        {
            const float4* wp = (const float4*)sW;
            float4 w0 = wp[0], w1 = wp[1], w2 = wp[2], w3 = wp[3];
            float Wv[16] = { w0.x,w0.y,w0.z,w0.w, w1.x,w1.y,w1.z,w1.w,
                             w2.x,w2.y,w2.z,w2.w, w3.x,w3.y,w3.z,w3.w };
            float Us = U * (1.f / 256.f);
            #pragma unroll
            for (int j = 0; j < 16; j++)
                dT[j] = Us * Kr[j] * Wv[j] - T[j];
        }
        __syncthreads();   // done with sW / sT(Kr) reads

        // ===== F: D = C1 @ dT @ C2^T =====
        {
            float4* st = (float4*)(sT + tid * STR);
            st[0] = make_float4(dT[0], dT[1], dT[2], dT[3]);
            st[1] = make_float4(dT[4], dT[5], dT[6], dT[7]);
            st[2] = make_float4(dT[8], dT[9], dT[10], dT[11]);
            st[3] = make_float4(dT[12], dT[13], dT[14], dT[15]);
        }
        __syncthreads();
        float Rd[16];
        spmm_row(sT, ebase, cnt, tid, Rd);
        float D[16];
        #pragma unroll
        for (int jj = 0; jj < 16; jj++) {
            float s = 0.f;
            #pragma unroll
            for (int l4 = 0; l4 < 4; l4++) {
                float4 c4 = ((const float4*)sC2)[jj * 4 + l4];
                s += Rd[l4 * 4 + 0] * c4.x + Rd[l4 * 4 + 1] * c4.y
                   + Rd[l4 * 4 + 2] * c4.z + Rd[l4 * 4 + 3] * c4.w;
            }
            D[jj] = s;
        }

        // ===== G: line search =====
        float pa = 0.f, pb1 = 0.f, pb2 = 0.f, pb3 = 0.f;
        {
            const float* mp = g_Mr + sbase;
            const float* cp = g_CT + sbase;
            #pragma unroll
            for (int j = 0; j < 16; j++) {
                pa  += D[j] * dT[j];
                pb1 += mp[j] * dT[j];
                pb2 += D[j] * T[j];
                pb3 += cp[j] * dT[j];
            }
        }
        #pragma unroll
        for (int o = 16; o; o >>= 1) {
            pa  += __shfl_xor_sync(0xffffffffu, pa, o);
            pb1 += __shfl_xor_sync(0xffffffffu, pb1, o);
            pb2 += __shfl_xor_sync(0xffffffffu, pb2, o);
            pb3 += __shfl_xor_sync(0xffffffffu, pb3, o);
        }
        if (lane == 0) {
            sPart[wid * 4 + 0] = pa;  sPart[wid * 4 + 1] = pb1;
            sPart[wid * 4 + 2] = pb2; sPart[wid * 4 + 3] = pb3;
        }
        __syncthreads();
        if (tid == 0) {
            float Sa = 0.f, S1 = 0.f, S2 = 0.f, S3 = 0.f;
            #pragma unroll
            for (int w = 0; w < 8; w++) {
                Sa += sPart[w * 4 + 0]; S1 += sPart[w * 4 + 1];
                S2 += sPart[w * 4 + 2]; S3 += sPart[w * 4 + 3];
            }
            float A  = -2.f * alpha * Sa;
            float Bc = (1.f - alpha) * S1 - 2.f * alpha * (S2 + S3);
            float tstep;
            if (A > 0.f) {
                tstep = -Bc / (2.f * A + 1e-16f);
                tstep = fminf(1.f, fmaxf(0.f, tstep));
            } else {
                tstep = (A + Bc < 0.f) ? 1.f : 0.f;
            }
            sScal[1] = tstep;
        }
        __syncthreads();
        float ts = sScal[1];
        #pragma unroll
        for (int j = 0; j < 16; j++) T[j] += ts * dT[j];
    }

    // ===== epilogue =====
    float pg = 0.f, pl = 0.f;
    {
        const float* mp = g_Mr + sbase;
        #pragma unroll
        for (int j = 0; j < 16; j++) {
            pg += (cc1 + scc2[j] - 2.f * CTC[j]) * T[j];
            pl += mp[j] * T[j];
        }
    }
    #pragma unroll
    for (int o = 16; o; o >>= 1) {
        pg += __shfl_xor_sync(0xffffffffu, pg, o);
        pl += __shfl_xor_sync(0xffffffffu, pl, o);
    }
    if (lane == 0) { sPart[wid * 2] = pg; sPart[wid * 2 + 1] = pl; }
    __syncthreads();
    if (tid == 0) {
        float Gw = 0.f, L = 0.f;
        #pragma unroll
        for (int w = 0; w < 8; w++) { Gw += sPart[w * 2]; L += sPart[w * 2 + 1]; }
        out[bid] = (1.f - alpha) * L + alpha * Gw;
    }
}

// ============================ launch ============================

extern "C" void kernel_launch(void* const* d_in, const int* in_sizes, int n_in,
                              void* d_out, int out_size)
{
    const float* x  = (const float*)d_in[0];
    const int*   ei = (const int*)  d_in[1];
    const float* tA = (const float*)d_in[3];
    const float* tF = (const float*)d_in[4];
    const float* q0 = (const float*)d_in[5];
    const float* a0 = (const float*)d_in[6];
    int E = in_sizes[1] / 2;

    k_zero<<<8192, 256>>>();
    k_scatter<<<(E + 255) / 256, 256>>>(ei, E);
    k_csr<<<(Bg * Nn * 32 + 255) / 256, 256>>>();
    k_fgw<<<Bg * Kk, 256>>>(x, tA, tF, q0, a0, (float*)d_out);
}

// round 6
// speedup vs baseline: 3.8706x; 1.6293x over previous
#include <cuda_runtime.h>
#include <cstdint>
#include <cstddef>

// ---- static problem sizes (match reference) ----
#define Bg 128
#define Nn 256
#define Dd 128
#define Kk 16
#define Mm 16
#define CG_ITERS 10
#define SINK_ITERS 50
#define CAP 128
#define STR 20           // smem staging stride in floats (80B, 16B-aligned)
#define PROB (Bg * Kk)

#define FPAD(i) ((i) + 4 * ((i) >> 4))   // padded index: 16-blocks at stride 20

// ---- device scratch (no cudaMalloc anywhere) ----
__device__ float           g_C[(size_t)Bg * Nn * Nn];
__device__ float           g_val[(size_t)Bg * CAP * Nn];   // ELL TRANSPOSED: [b][e][row]
__device__ unsigned short  g_col[(size_t)Bg * CAP * Nn];   // [b][e][row]
__device__ int             g_cnt[Bg * Nn];
__device__ float           g_cc1[Bg * Nn];
__device__ float           g_Mr[(size_t)PROB * Nn * Mm];   // Mcost spill (per-thread)
__device__ float           g_CT[(size_t)PROB * Nn * Mm];   // CTC spill (per-thread)

// ============================ precompute ============================

__global__ void k_zero()
{
    size_t n = (size_t)Bg * Nn * Nn;
    for (size_t i = (size_t)blockIdx.x * blockDim.x + threadIdx.x; i < n;
         i += (size_t)gridDim.x * blockDim.x)
        g_C[i] = 0.f;
}

__global__ void k_scatter(const int* __restrict__ ei, int E)
{
    int e = blockIdx.x * blockDim.x + threadIdx.x;
    if (e >= E) return;
    int s = ei[e];
    int t = ei[E + e];
    int g = s >> 8;
    atomicAdd(&g_C[((size_t)(g * Nn + (s & 255))) * Nn + (t & 255)], 1.f);
}

// one warp per row: ballot-compaction into TRANSPOSED ELL [b][e][row]
__global__ void k_csr()
{
    int w = (blockIdx.x * blockDim.x + threadIdx.x) >> 5;
    int lane = threadIdx.x & 31;
    if (w >= Bg * Nn) return;
    int b = w >> 8, row = w & 255;
    const float* Crow = g_C + (size_t)w * Nn;
    float s2 = 0.f;
    int out = 0;
    size_t base = (size_t)b * CAP * Nn + row;
    for (int c0 = 0; c0 < Nn; c0 += 32) {
        float v = Crow[c0 + lane];
        s2 += v * v;
        unsigned m = __ballot_sync(0xffffffffu, v != 0.f);
        int off = __popc(m & ((1u << lane) - 1u));
        if (v != 0.f && (out + off) < CAP) {
            g_val[base + (size_t)(out + off) * Nn] = v;
            g_col[base + (size_t)(out + off) * Nn] = (unsigned short)(c0 + lane);
        }
        out += __popc(m);
    }
    #pragma unroll
    for (int o = 16; o; o >>= 1) s2 += __shfl_xor_sync(0xffffffffu, s2, o);
    if (lane == 0) {
        g_cnt[w] = out > CAP ? CAP : out;
        g_cc1[w] = s2 * (1.f / Nn);
    }
}

// ============================ main kernel ============================

__device__ __forceinline__ float ex2(float x)
{
    float r; asm("ex2.approx.ftz.f32 %0, %1;" : "=f"(r) : "f"(x)); return r;
}
__device__ __forceinline__ float rcpa(float x)
{
    float r; asm("rcp.approx.ftz.f32 %0, %1;" : "=f"(r) : "f"(x)); return r;
}

// sparse row gather with coalesced ELL loads
__device__ __forceinline__ void spmm_row(const float* sT, size_t ebase, int cnt,
                                         int tid, float R[16])
{
    #pragma unroll
    for (int j = 0; j < 16; j++) R[j] = 0.f;
    size_t idx = ebase + tid;
    for (int e = 0; e < cnt; e++, idx += Nn) {
        int   c  = g_col[idx];
        float vv = g_val[idx];
        const float4* tp = (const float4*)(sT + c * STR);
        float4 t0 = tp[0], t1 = tp[1], t2 = tp[2], t3 = tp[3];
        R[0]  += vv * t0.x; R[1]  += vv * t0.y; R[2]  += vv * t0.z; R[3]  += vv * t0.w;
        R[4]  += vv * t1.x; R[5]  += vv * t1.y; R[6]  += vv * t1.z; R[7]  += vv * t1.w;
        R[8]  += vv * t2.x; R[9]  += vv * t2.y; R[10] += vv * t2.z; R[11] += vv * t2.w;
        R[12] += vv * t3.x; R[13] += vv * t3.y; R[14] += vv * t3.z; R[15] += vv * t3.w;
    }
}

__global__ __launch_bounds__(256, 3)
void k_fgw(const float* __restrict__ x,
           const float* __restrict__ tA,
           const float* __restrict__ tF,
           const float* __restrict__ q0,
           const float* __restrict__ a0,
           float* __restrict__ out)
{
    __shared__ __align__(16) float sT[Nn * STR];       // staging (Kr / T / dT / features)
    __shared__ __align__(16) float sU[Nn + Nn / 4];    // padded u buffer
    __shared__ __align__(16) float sW[Mm];             // scaled v
    __shared__ __align__(16) float sPart[8 * Mm];      // per-warp column partials
    __shared__ __align__(16) float sC2[Mm * Mm];
    __shared__ float scc2[Mm];
    __shared__ float sq256[Mm];                        // 256 * q_j
    __shared__ float sq[Mm];
    __shared__ float sFn[Mm];
    __shared__ float sred[8];
    __shared__ float sScal[4];
    __shared__ int   sChg;                             // Sinkhorn convergence flag

    const int tid  = threadIdx.x;
    const int bid  = blockIdx.x;
    const int b    = bid >> 4;
    const int k    = bid & 15;
    const int lane = tid & 31;
    const int wid  = tid >> 5;
    const float L2E = 1.44269504088896340736f;

    const float alpha = 1.f / (1.f + expf(-a0[0]));
    const size_t sbase = ((size_t)bid * Nn + tid) * Mm;       // spill base
    const size_t ebase = (size_t)b * CAP * Nn;                // ELL base

    // --- load C2, q softmax, features ---
    sC2[tid] = tA[k * 256 + tid];
    if (tid == 0) {
        float qv[16], mq = -1e30f;
        #pragma unroll
        for (int j = 0; j < 16; j++) { qv[j] = q0[k * 16 + j]; mq = fmaxf(mq, qv[j]); }
        float s = 0.f;
        #pragma unroll
        for (int j = 0; j < 16; j++) { qv[j] = ex2((qv[j] - mq) * L2E); s += qv[j]; }
        float inv = 1.f / s;
        #pragma unroll
        for (int j = 0; j < 16; j++) {
            float qq = qv[j] * inv;
            sq[j] = qq;
            sq256[j] = 256.f * qq;
        }
    }
    for (int t = tid; t < Mm * Dd; t += 256) sT[t] = tF[k * Mm * Dd + t];
    __syncthreads();

    if (tid < 16) {
        float s = 0.f;
        #pragma unroll
        for (int l = 0; l < 16; l++) { float c = sC2[tid * 16 + l]; s += c * c * sq[l]; }
        scc2[tid] = s;
        float fn = 0.f;
        for (int d = 0; d < Dd; d++) { float f = sT[tid * Dd + d]; fn += f * f; }
        sFn[tid] = fn;
    }

    // --- Mcost row -> spill to g_Mr ---
    {
        float Mr[16];
        #pragma unroll
        for (int j = 0; j < 16; j++) Mr[j] = 0.f;
        float xn = 0.f;
        const float4* xr = (const float4*)(x + ((size_t)(b * Nn + tid)) * Dd);
        for (int d4 = 0; d4 < Dd / 4; d4++) {
            float4 xv = xr[d4];
            xn += xv.x * xv.x + xv.y * xv.y + xv.z * xv.z + xv.w * xv.w;
            #pragma unroll
            for (int j = 0; j < 16; j++) {
                float4 fv = ((const float4*)sT)[j * (Dd / 4) + d4];
                Mr[j] += xv.x * fv.x + xv.y * fv.y + xv.z * fv.z + xv.w * fv.w;
            }
        }
        __syncthreads();
        float4* mp = (float4*)(g_Mr + sbase);
        #pragma unroll
        for (int j4 = 0; j4 < 4; j4++) {
            float4 v;
            v.x = xn + sFn[j4 * 4 + 0] - 2.f * Mr[j4 * 4 + 0];
            v.y = xn + sFn[j4 * 4 + 1] - 2.f * Mr[j4 * 4 + 1];
            v.z = xn + sFn[j4 * 4 + 2] - 2.f * Mr[j4 * 4 + 2];
            v.w = xn + sFn[j4 * 4 + 3] - 2.f * Mr[j4 * 4 + 3];
            mp[j4] = v;
        }
    }

    const int grow = b * Nn + tid;
    const int cnt = g_cnt[grow];
    const float cc1 = g_cc1[grow];

    float T[16];
    #pragma unroll
    for (int j = 0; j < 16; j++) T[j] = sq[j] * (1.f / Nn);

    float CTC[16];
    const int cs2 = tid >> 4;        // col thread: 16-row block index
    const int cj2 = tid & 15;        // col thread: column

    for (int it = 0; it <= CG_ITERS; it++) {
        // ===== A: CTC = C1 @ T @ C2^T =====
        {
            float4* st = (float4*)(sT + tid * STR);
            st[0] = make_float4(T[0], T[1], T[2], T[3]);
            st[1] = make_float4(T[4], T[5], T[6], T[7]);
            st[2] = make_float4(T[8], T[9], T[10], T[11]);
            st[3] = make_float4(T[12], T[13], T[14], T[15]);
        }
        __syncthreads();
        float R[16];
        spmm_row(sT, ebase, cnt, tid, R);
        #pragma unroll
        for (int jj = 0; jj < 16; jj++) {
            float s = 0.f;
            #pragma unroll
            for (int l4 = 0; l4 < 4; l4++) {
                float4 c4 = ((const float4*)sC2)[jj * 4 + l4];
                s += R[l4 * 4 + 0] * c4.x + R[l4 * 4 + 1] * c4.y
                   + R[l4 * 4 + 2] * c4.z + R[l4 * 4 + 3] * c4.w;
            }
            CTC[jj] = s;
        }
        if (it == CG_ITERS) break;

        // ===== B: gradient -> Kr, spill CTC, block max|grad| =====
        float Kr[16];
        float mxa = 0.f;
        {
            float4* cp = (float4*)(g_CT + sbase);
            #pragma unroll
            for (int j = 0; j < 16; j++) {
                float m = ((const float*)(g_Mr + sbase))[j];
                float g = (1.f - alpha) * m + 2.f * alpha * (cc1 + scc2[j] - 2.f * CTC[j]);
                Kr[j] = g;                        // temporarily holds grad
                mxa = fmaxf(mxa, fabsf(g));
            }
            #pragma unroll
            for (int j4 = 0; j4 < 4; j4++)
                cp[j4] = make_float4(CTC[j4*4+0], CTC[j4*4+1], CTC[j4*4+2], CTC[j4*4+3]);
        }
        #pragma unroll
        for (int o = 16; o; o >>= 1) mxa = fmaxf(mxa, __shfl_xor_sync(0xffffffffu, mxa, o));
        if (lane == 0) sred[wid] = mxa;
        __syncthreads();
        {
            float m = fmaxf(fmaxf(fmaxf(sred[0], sred[1]), fmaxf(sred[2], sred[3])),
                            fmaxf(fmaxf(sred[4], sred[5]), fmaxf(sred[6], sred[7])));
            float cscale = -L2E / (0.01f * m + 1e-12f);
            float rmax = -1e30f;
            #pragma unroll
            for (int j = 0; j < 16; j++) { Kr[j] *= cscale; rmax = fmaxf(rmax, Kr[j]); }
            #pragma unroll
            for (int j = 0; j < 16; j++) Kr[j] = ex2(Kr[j] - rmax);   // Kr in (0,1]
        }
        __syncthreads();   // sred read done; sT free

        // ===== C: stage Kr, read transposed copy (Kc_t) =====
        {
            float4* st = (float4*)(sT + tid * STR);
            st[0] = make_float4(Kr[0], Kr[1], Kr[2], Kr[3]);
            st[1] = make_float4(Kr[4], Kr[5], Kr[6], Kr[7]);
            st[2] = make_float4(Kr[8], Kr[9], Kr[10], Kr[11]);
            st[3] = make_float4(Kr[12], Kr[13], Kr[14], Kr[15]);
        }
        if (tid < 16) sW[tid] = 1.f;
        if (tid == 0) sChg = 1;
        __syncthreads();
        float Kc_t[16];
        #pragma unroll
        for (int r = 0; r < 16; r++)
            Kc_t[r] = sT[(cs2 * 16 + r) * STR + cj2];
        // no barrier needed: sT not rewritten until after sink loop

        // ===== D: Sinkhorn, scale-free linear domain, with convergence exit =====
        float U = 0.f;
        for (int sk = 0; sk < SINK_ITERS; sk++) {
            // row: u = 1 / (Kr . W)
            {
                const float4* wp = (const float4*)sW;
                float4 w0 = wp[0], w1 = wp[1], w2 = wp[2], w3 = wp[3];
                float s0 = Kr[0]  * w0.x + Kr[1]  * w0.y + Kr[2]  * w0.z + Kr[3]  * w0.w;
                float s1 = Kr[4]  * w1.x + Kr[5]  * w1.y + Kr[6]  * w1.z + Kr[7]  * w1.w;
                float s2 = Kr[8]  * w2.x + Kr[9]  * w2.y + Kr[10] * w2.z + Kr[11] * w2.w;
                float s3 = Kr[12] * w3.x + Kr[13] * w3.y + Kr[14] * w3.z + Kr[15] * w3.w;
                float s = fmaxf((s0 + s1) + (s2 + s3), 1e-30f);
                U = rcpa(s);
                sU[FPAD(tid)] = U;
            }
            __syncthreads();
            // col: partial_{cj2} = sum over 16 rows of block cs2
            {
                const float4* up = (const float4*)(sU + cs2 * STR);
                float4 a = up[0], bb = up[1], c = up[2], d = up[3];
                float part = Kc_t[0]  * a.x  + Kc_t[1]  * a.y  + Kc_t[2]  * a.z  + Kc_t[3]  * a.w
                           + Kc_t[4]  * bb.x + Kc_t[5]  * bb.y + Kc_t[6]  * bb.z + Kc_t[7]  * bb.w
                           + Kc_t[8]  * c.x  + Kc_t[9]  * c.y  + Kc_t[10] * c.z  + Kc_t[11] * c.w
                           + Kc_t[12] * d.x  + Kc_t[13] * d.y  + Kc_t[14] * d.z  + Kc_t[15] * d.w;
                part += __shfl_xor_sync(0xffffffffu, part, 16);   // pair cs2 blocks in warp
                if (lane < 16) sPart[wid * 16 + lane] = part;
            }
            __syncthreads();
            // tail: P_j over 8 warps, W_j = 256 q_j / P_j ; convergence ballot
            if (tid < 16) {
                float P = sPart[tid] + sPart[16 + tid] + sPart[32 + tid] + sPart[48 + tid]
                        + sPart[64 + tid] + sPart[80 + tid] + sPart[96 + tid] + sPart[112 + tid];
                float Wo = sW[tid];
                float Wn = sq256[tid] * rcpa(fmaxf(P, 1e-30f));
                unsigned chg = __ballot_sync(0x0000ffffu,
                                             fabsf(Wn - Wo) > 1e-6f * Wo);
                sW[tid] = Wn;
                if (tid == 0) sChg = (int)chg;
            }
            __syncthreads();
            if (sChg == 0) break;     // converged: remaining iters are numeric no-ops
        }

        // ===== E: Tnew = (1/256) * U * Kr * W ; dT =====
        float dT[16];
        {
            const float4* wp = (const float4*)sW;
            float4 w0 = wp[0], w1 = wp[1], w2 = wp[2], w3 = wp[3];
            float Wv[16] = { w0.x,w0.y,w0.z,w0.w, w1.x,w1.y,w1.z,w1.w,
                             w2.x,w2.y,w2.z,w2.w, w3.x,w3.y,w3.z,w3.w };
            float Us = U * (1.f / 256.f);
            #pragma unroll
            for (int j = 0; j < 16; j++)
                dT[j] = Us * Kr[j] * Wv[j] - T[j];
        }
        __syncthreads();   // done with sW / sT(Kr) reads

        // ===== F: D = C1 @ dT @ C2^T =====
        {
            float4* st = (float4*)(sT + tid * STR);
            st[0] = make_float4(dT[0], dT[1], dT[2], dT[3]);
            st[1] = make_float4(dT[4], dT[5], dT[6], dT[7]);
            st[2] = make_float4(dT[8], dT[9], dT[10], dT[11]);
            st[3] = make_float4(dT[12], dT[13], dT[14], dT[15]);
        }
        __syncthreads();
        float Rd[16];
        spmm_row(sT, ebase, cnt, tid, Rd);
        float D[16];
        #pragma unroll
        for (int jj = 0; jj < 16; jj++) {
            float s = 0.f;
            #pragma unroll
            for (int l4 = 0; l4 < 4; l4++) {
                float4 c4 = ((const float4*)sC2)[jj * 4 + l4];
                s += Rd[l4 * 4 + 0] * c4.x + Rd[l4 * 4 + 1] * c4.y
                   + Rd[l4 * 4 + 2] * c4.z + Rd[l4 * 4 + 3] * c4.w;
            }
            D[jj] = s;
        }

        // ===== G: line search =====
        float pa = 0.f, pb1 = 0.f, pb2 = 0.f, pb3 = 0.f;
        {
            const float* mp = g_Mr + sbase;
            const float* cp = g_CT + sbase;
            #pragma unroll
            for (int j = 0; j < 16; j++) {
                pa  += D[j] * dT[j];
                pb1 += mp[j] * dT[j];
                pb2 += D[j] * T[j];
                pb3 += cp[j] * dT[j];
            }
        }
        #pragma unroll
        for (int o = 16; o; o >>= 1) {
            pa  += __shfl_xor_sync(0xffffffffu, pa, o);
            pb1 += __shfl_xor_sync(0xffffffffu, pb1, o);
            pb2 += __shfl_xor_sync(0xffffffffu, pb2, o);
            pb3 += __shfl_xor_sync(0xffffffffu, pb3, o);
        }
        if (lane == 0) {
            sPart[wid * 4 + 0] = pa;  sPart[wid * 4 + 1] = pb1;
            sPart[wid * 4 + 2] = pb2; sPart[wid * 4 + 3] = pb3;
        }
        __syncthreads();
        if (tid == 0) {
            float Sa = 0.f, S1 = 0.f, S2 = 0.f, S3 = 0.f;
            #pragma unroll
            for (int w = 0; w < 8; w++) {
                Sa += sPart[w * 4 + 0]; S1 += sPart[w * 4 + 1];
                S2 += sPart[w * 4 + 2]; S3 += sPart[w * 4 + 3];
            }
            float A  = -2.f * alpha * Sa;
            float Bc = (1.f - alpha) * S1 - 2.f * alpha * (S2 + S3);
            float tstep;
            if (A > 0.f) {
                tstep = -Bc / (2.f * A + 1e-16f);
                tstep = fminf(1.f, fmaxf(0.f, tstep));
            } else {
                tstep = (A + Bc < 0.f) ? 1.f : 0.f;
            }
            sScal[1] = tstep;
        }
        __syncthreads();
        float ts = sScal[1];
        #pragma unroll
        for (int j = 0; j < 16; j++) T[j] += ts * dT[j];
        // ts == 0  =>  T unchanged  =>  every remaining CG iteration is an exact
        // no-op (same grad -> same plan -> same ts). CTC in regs is C1@T@C2^T
        // for the final T (computed this iteration, T unchanged since).
        if (ts == 0.f) break;
    }

    // ===== epilogue =====
    float pg = 0.f, pl = 0.f;
    {
        const float* mp = g_Mr + sbase;
        #pragma unroll
        for (int j = 0; j < 16; j++) {
            pg += (cc1 + scc2[j] - 2.f * CTC[j]) * T[j];
            pl += mp[j] * T[j];
        }
    }
    #pragma unroll
    for (int o = 16; o; o >>= 1) {
        pg += __shfl_xor_sync(0xffffffffu, pg, o);
        pl += __shfl_xor_sync(0xffffffffu, pl, o);
    }
    if (lane == 0) { sPart[wid * 2] = pg; sPart[wid * 2 + 1] = pl; }
    __syncthreads();
    if (tid == 0) {
        float Gw = 0.f, L = 0.f;
        #pragma unroll
        for (int w = 0; w < 8; w++) { Gw += sPart[w * 2]; L += sPart[w * 2 + 1]; }
        out[bid] = (1.f - alpha) * L + alpha * Gw;
    }
}

// ============================ launch ============================

extern "C" void kernel_launch(void* const* d_in, const int* in_sizes, int n_in,
                              void* d_out, int out_size)
{
    const float* x  = (const float*)d_in[0];
    const int*   ei = (const int*)  d_in[1];
    const float* tA = (const float*)d_in[3];
    const float* tF = (const float*)d_in[4];
    const float* q0 = (const float*)d_in[5];
    const float* a0 = (const float*)d_in[6];
    int E = in_sizes[1] / 2;

    k_zero<<<8192, 256>>>();
    k_scatter<<<(E + 255) / 256, 256>>>(ei, E);
    k_csr<<<(Bg * Nn * 32 + 255) / 256, 256>>>();
    k_fgw<<<Bg * Kk, 256>>>(x, tA, tF, q0, a0, (float*)d_out);
}